// round 11
// baseline (speedup 1.0000x reference)
#include <cuda_runtime.h>
#include <cuda_fp16.h>
#include <math.h>

#define NMAX 100000
#define EMAX 1600000
#define FD 128
#define HD 128
#define CD 40
#define NLAY 4

// ---- static device scratch ----
// Invariant: g_cnt, g_stats, g_done are zero at entry of every kernel_launch
// call (zero at module load; each call re-zeroes them after use).
__device__ __half g_xw[(size_t)NMAX * HD];     // fp16: halves gather L2 traffic
__device__ float g_agg[NLAY][(size_t)NMAX * HD];
__device__ float g_out[(size_t)NMAX * CD];     // running sum of class heads
__device__ int   g_cnt[NMAX];
__device__ float g_dinv[NMAX];
__device__ int   g_off[NMAX + 1];
__device__ int   g_cur[NMAX];
__device__ int   g_csrc[EMAX];
__device__ float g_cval[EMAX];
__device__ float g_stats[NLAY][2 * HD];
__device__ float g_scale[NLAY][HD];
__device__ float g_sbias[NLAY][HD];
__device__ int   g_done[NLAY];

// ---- packed f32x2 helpers ----
__device__ __forceinline__ unsigned long long pk2(float lo, float hi) {
    unsigned long long r;
    asm("mov.b64 %0, {%1, %2};" : "=l"(r) : "f"(lo), "f"(hi));
    return r;
}
__device__ __forceinline__ void fma2(unsigned long long& d,
                                     unsigned long long a, unsigned long long b) {
    asm("fma.rn.f32x2 %0, %1, %2, %0;" : "+l"(d) : "l"(a), "l"(b));
}
__device__ __forceinline__ float2 up2(unsigned long long v) {
    float2 r;
    asm("mov.b64 {%0, %1}, %2;" : "=f"(r.x), "=f"(r.y) : "l"(v));
    return r;
}

// ---- tf32 helpers (k_final) ----
__device__ __forceinline__ unsigned tf32_cvt(float f) {
    unsigned r;
    asm("cvt.rna.tf32.f32 %0, %1;" : "=r"(r) : "f"(f));
    return r;
}
__device__ __forceinline__ void mma_tf32(float* c, const unsigned* a, const unsigned* b) {
    asm("mma.sync.aligned.m16n8k8.row.col.f32.tf32.tf32.f32 "
        "{%0,%1,%2,%3}, {%4,%5,%6,%7}, {%8,%9}, {%0,%1,%2,%3};"
        : "+f"(c[0]), "+f"(c[1]), "+f"(c[2]), "+f"(c[3])
        : "r"(a[0]), "r"(a[1]), "r"(a[2]), "r"(a[3]), "r"(b[0]), "r"(b[1]));
}

// ---- fp16 m16n8k16 MMA (fp32 accum) ----
__device__ __forceinline__ void mma_f16(float* c, const unsigned* a, const unsigned* b) {
    asm("mma.sync.aligned.m16n8k16.row.col.f32.f16.f16.f32 "
        "{%0,%1,%2,%3}, {%4,%5,%6,%7}, {%8,%9}, {%0,%1,%2,%3};"
        : "+f"(c[0]), "+f"(c[1]), "+f"(c[2]), "+f"(c[3])
        : "r"(a[0]), "r"(a[1]), "r"(a[2]), "r"(a[3]), "r"(b[0]), "r"(b[1]));
}

// ---------------------------------------------------------------------------
__global__ void k_hist(const int* __restrict__ dst, int e) {
    int i = blockIdx.x * blockDim.x + threadIdx.x;
    if (i < e) atomicAdd(&g_cnt[dst[i]], 1);
}

__global__ void k_scan(int n) {
    __shared__ int sp[1024];
    int t = threadIdx.x;
    int chunk = (n + 1023) >> 10;
    int beg = t * chunk;
    int end = min(beg + chunk, n);
    int s = 0;
    for (int j = beg; j < end; j++) s += g_cnt[j];
    sp[t] = s;
    __syncthreads();
    for (int d = 1; d < 1024; d <<= 1) {
        int tmp = (t >= d) ? sp[t - d] : 0;
        __syncthreads();
        sp[t] += tmp;
        __syncthreads();
    }
    int base = sp[t] - s;
    for (int j = beg; j < end; j++) {
        int c = g_cnt[j];
        g_cnt[j] = 0;  // self-reset
        g_off[j] = base;
        g_cur[j] = base;
        g_dinv[j] = rsqrtf((float)c + 2.0f);
        base += c;
    }
    if (end == n) g_off[n] = base;
}

__global__ void k_fill(const int* __restrict__ src, const int* __restrict__ dst, int e) {
    int i = blockIdx.x * blockDim.x + threadIdx.x;
    if (i < e) {
        int d = dst[i];
        int s = src[i];
        int p = atomicAdd(&g_cur[d], 1);
        g_csrc[p] = s;
        g_cval[p] = g_dinv[s];
    }
}

// ---------------------------------------------------------------------------
// Conv SGEMM via SPLIT-FP16 m16n8k16 tensor MMA (a=ahi+alo, 3 cross terms,
// ~2^-23 accuracy) fused with per-layer class head (ahi+alo vs fp16-hi B).
// hi/lo split done ONCE at staging into fp16 smem; inner loop = LDS + HMMA.
//   g_xw (fp16) = A @ conv_w[layer]      (A = outs[layer], BN+ReLU on load)
//   g_out (+)= A @ fc_w[layer]
__global__ __launch_bounds__(512, 1) void k_gemm(const float* __restrict__ x,
                                                 const float* __restrict__ W,
                                                 const float* __restrict__ fw,
                                                 int layer, int n) {
    // A: [m][k] halves, cols 0-15 = hi, 16-31 = lo; stride 40 -> conflict-free
    __shared__ __align__(16) __half As2[2][128][40];
    // B: TRANSPOSED [n][k] halves, cols 0-15 = hi, 16-31 = lo; stride 40
    __shared__ __align__(16) __half Bs2[2][128][40];
    // head B: transposed [n][k] halves, hi only; stride 24 -> conflict-free
    __shared__ __align__(16) __half Hs2[2][40][24];
    const float* A  = (layer == 0) ? x : g_agg[layer - 1];
    const float* sc = (layer > 0) ? g_scale[layer - 1] : 0;
    const float* sb = (layer > 0) ? g_sbias[layer - 1] : 0;
    int tid = threadIdx.x;
    int lane = tid & 31, wid = tid >> 5;
    int g4 = lane >> 2, t4 = lane & 3;
    int wr = (wid >> 2) * 32, wc = (wid & 3) * 32;
    int hc = wid & 3;
    int ar = tid >> 2, akq = (tid & 3) * 4;
    int bk = tid >> 5, bn0 = (tid & 31) * 4;
    bool hldr = (tid < 160);
    int hkr = tid / 10, hnc = (tid % 10) * 4;
    int row0 = blockIdx.x * 128;
    int gr = row0 + ar;

    float acc[2][4][4];
#pragma unroll
    for (int mi = 0; mi < 2; mi++)
#pragma unroll
        for (int ni = 0; ni < 4; ni++)
#pragma unroll
            for (int q = 0; q < 4; q++) acc[mi][ni][q] = 0.f;
    float acch[2][2][4];
#pragma unroll
    for (int s = 0; s < 2; s++)
#pragma unroll
        for (int mi = 0; mi < 2; mi++)
#pragma unroll
            for (int q = 0; q < 4; q++) acch[s][mi][q] = 0.f;

    float4 pa, pb, ph;
    auto load_slab = [&](int s) {
        int k0 = s * 16;
        pa = make_float4(0.f, 0.f, 0.f, 0.f);
        if (gr < n) pa = *(const float4*)(A + (size_t)gr * HD + k0 + akq);
        if (layer > 0) {
            int kb = k0 + akq;
            pa.x = fmaxf(fmaf(pa.x, sc[kb + 0], sb[kb + 0]), 0.f);
            pa.y = fmaxf(fmaf(pa.y, sc[kb + 1], sb[kb + 1]), 0.f);
            pa.z = fmaxf(fmaf(pa.z, sc[kb + 2], sb[kb + 2]), 0.f);
            pa.w = fmaxf(fmaf(pa.w, sc[kb + 3], sb[kb + 3]), 0.f);
        }
        pb = *(const float4*)(W + (size_t)(k0 + bk) * HD + bn0);
        if (hldr)
            ph = *(const float4*)(fw + ((size_t)layer * HD + k0 + hkr) * CD + hnc);
    };
    auto store_slab = [&](int buf) {
        // A: hi/lo split, row-contiguous
        float av[4] = {pa.x, pa.y, pa.z, pa.w};
        __half ah[4], alo[4];
#pragma unroll
        for (int j = 0; j < 4; j++) {
            ah[j]  = __float2half_rn(av[j]);
            alo[j] = __float2half_rn(av[j] - __half2float(ah[j]));
        }
        *(__half2*)&As2[buf][ar][akq]          = *(__half2*)&ah[0];
        *(__half2*)&As2[buf][ar][akq + 2]      = *(__half2*)&ah[2];
        *(__half2*)&As2[buf][ar][16 + akq]     = *(__half2*)&alo[0];
        *(__half2*)&As2[buf][ar][16 + akq + 2] = *(__half2*)&alo[2];
        // B: hi/lo split, transposed scatter (staging only)
        float bv[4] = {pb.x, pb.y, pb.z, pb.w};
#pragma unroll
        for (int j = 0; j < 4; j++) {
            __half hv = __float2half_rn(bv[j]);
            Bs2[buf][bn0 + j][bk]      = hv;
            Bs2[buf][bn0 + j][16 + bk] = __float2half_rn(bv[j] - __half2float(hv));
        }
        if (hldr) {
            float hv4[4] = {ph.x, ph.y, ph.z, ph.w};
#pragma unroll
            for (int j = 0; j < 4; j++)
                Hs2[buf][hnc + j][hkr] = __float2half_rn(hv4[j]);
        }
    };

    load_slab(0);
    store_slab(0);
    __syncthreads();

#pragma unroll
    for (int ks = 0; ks < 8; ks++) {
        int buf = ks & 1;
        if (ks < 7) load_slab(ks + 1);
        // fragment loads (half2 per reg), k16 covers the whole slab
        unsigned ah[2][4], al[2][4], bh[4][2], bl[4][2];
#pragma unroll
        for (int mi = 0; mi < 2; mi++) {
            int m = wr + mi * 16 + g4;
            ah[mi][0] = *(const unsigned*)&As2[buf][m][2 * t4];
            ah[mi][1] = *(const unsigned*)&As2[buf][m + 8][2 * t4];
            ah[mi][2] = *(const unsigned*)&As2[buf][m][8 + 2 * t4];
            ah[mi][3] = *(const unsigned*)&As2[buf][m + 8][8 + 2 * t4];
            al[mi][0] = *(const unsigned*)&As2[buf][m][16 + 2 * t4];
            al[mi][1] = *(const unsigned*)&As2[buf][m + 8][16 + 2 * t4];
            al[mi][2] = *(const unsigned*)&As2[buf][m][24 + 2 * t4];
            al[mi][3] = *(const unsigned*)&As2[buf][m + 8][24 + 2 * t4];
        }
#pragma unroll
        for (int ni = 0; ni < 4; ni++) {
            int nn = wc + ni * 8 + g4;
            bh[ni][0] = *(const unsigned*)&Bs2[buf][nn][2 * t4];
            bh[ni][1] = *(const unsigned*)&Bs2[buf][nn][8 + 2 * t4];
            bl[ni][0] = *(const unsigned*)&Bs2[buf][nn][16 + 2 * t4];
            bl[ni][1] = *(const unsigned*)&Bs2[buf][nn][24 + 2 * t4];
        }
        // conv: 3 cross terms per tile
#pragma unroll
        for (int mi = 0; mi < 2; mi++)
#pragma unroll
            for (int ni = 0; ni < 4; ni++) {
                mma_f16(acc[mi][ni], ah[mi], bh[ni]);
                mma_f16(acc[mi][ni], ah[mi], bl[ni]);
                mma_f16(acc[mi][ni], al[mi], bh[ni]);
            }
        // head: (ahi+alo) x bhi
        {
            unsigned hb[2];
            hb[0] = *(const unsigned*)&Hs2[buf][hc * 8 + g4][2 * t4];
            hb[1] = *(const unsigned*)&Hs2[buf][hc * 8 + g4][8 + 2 * t4];
#pragma unroll
            for (int mi = 0; mi < 2; mi++) {
                mma_f16(acch[0][mi], ah[mi], hb);
                mma_f16(acch[0][mi], al[mi], hb);
            }
            if (hc == 3) {
                unsigned hb4[2];
                hb4[0] = *(const unsigned*)&Hs2[buf][32 + g4][2 * t4];
                hb4[1] = *(const unsigned*)&Hs2[buf][32 + g4][8 + 2 * t4];
#pragma unroll
                for (int mi = 0; mi < 2; mi++) {
                    mma_f16(acch[1][mi], ah[mi], hb4);
                    mma_f16(acch[1][mi], al[mi], hb4);
                }
            }
        }
        if (ks < 7) {
            store_slab(buf ^ 1);
            __syncthreads();
        }
    }
    // conv epilogue: write fp16 (half2 per 2 cols)
#pragma unroll
    for (int mi = 0; mi < 2; mi++) {
#pragma unroll
        for (int ni = 0; ni < 4; ni++) {
            int r = row0 + wr + mi * 16 + g4;
            int c = wc + ni * 8 + t4 * 2;
            if (r < n)
                *(__half2*)(g_xw + (size_t)r * HD + c) =
                    __floats2half2_rn(acc[mi][ni][0], acc[mi][ni][1]);
            if (r + 8 < n)
                *(__half2*)(g_xw + (size_t)(r + 8) * HD + c) =
                    __floats2half2_rn(acc[mi][ni][2], acc[mi][ni][3]);
        }
    }
    // head epilogue: unique (row, tile) ownership -> plain RMW, no atomics
    int nslots = (hc == 3) ? 2 : 1;
    for (int s = 0; s < nslots; s++) {
        int tile = (s == 0) ? hc : 4;
        int c = tile * 8 + t4 * 2;
#pragma unroll
        for (int mi = 0; mi < 2; mi++) {
#pragma unroll
            for (int half = 0; half < 2; half++) {
                int r = row0 + wr + mi * 16 + half * 8 + g4;
                if (r < n) {
                    float2 val = make_float2(acch[s][mi][half * 2 + 0],
                                             acch[s][mi][half * 2 + 1]);
                    float2* p = (float2*)(g_out + (size_t)r * CD + c);
                    if (layer == 0) {
                        *p = val;
                    } else {
                        float2 o = *p;
                        *p = make_float2(o.x + val.x, o.y + val.y);
                    }
                }
            }
        }
    }
}

// ---------------------------------------------------------------------------
// Aggregation: warp per node; lane owns 4 columns; unroll-8 fp16 gather,
// fp32 accumulate. BN stats + fused scale/bias in last block. (unchanged)
__global__ __launch_bounds__(256) void k_agg(int layer, const float* __restrict__ convb,
                                             const float* __restrict__ bn_g,
                                             const float* __restrict__ bn_b, int n) {
    __shared__ float s_sum[128], s_sq[128];
    __shared__ int s_last;
    int tid = threadIdx.x;
    if (tid < 128) { s_sum[tid] = 0.f; s_sq[tid] = 0.f; }
    __syncthreads();

    int lane = tid & 31;
    int warp = tid >> 5;
    int c4 = lane * 4;
    float4 b4 = *(const float4*)(convb + c4);
    float* out = g_agg[layer];

    int gw = blockIdx.x * 8 + warp;
    int nw = gridDim.x * 8;

    float ls0 = 0.f, ls1 = 0.f, ls2 = 0.f, ls3 = 0.f;
    float lq0 = 0.f, lq1 = 0.f, lq2 = 0.f, lq3 = 0.f;

    for (int v = gw; v < n; v += nw) {
        int r0 = g_off[v], r1 = g_off[v + 1];
        float dv = g_dinv[v];
        unsigned long long p0 = 0ull, p1 = 0ull;
        int j = r0;
        for (; j + 7 < r1; j += 8) {
            int   si[8];
            float wi[8];
#pragma unroll
            for (int u = 0; u < 8; u++) { si[u] = g_csrc[j + u]; wi[u] = g_cval[j + u]; }
            uint2 hx[8];
#pragma unroll
            for (int u = 0; u < 8; u++)
                hx[u] = *(const uint2*)(g_xw + (size_t)si[u] * HD + c4);
#pragma unroll
            for (int u = 0; u < 8; u++) {
                float2 f0 = __half22float2(*(__half2*)&hx[u].x);
                float2 f1 = __half22float2(*(__half2*)&hx[u].y);
                unsigned long long wd = pk2(wi[u], wi[u]);
                fma2(p0, wd, pk2(f0.x, f0.y));
                fma2(p1, wd, pk2(f1.x, f1.y));
            }
        }
        for (; j < r1; j++) {
            int s0 = g_csrc[j];
            float w0 = g_cval[j];
            uint2 hx = *(const uint2*)(g_xw + (size_t)s0 * HD + c4);
            float2 f0 = __half22float2(*(__half2*)&hx.x);
            float2 f1 = __half22float2(*(__half2*)&hx.y);
            unsigned long long wd0 = pk2(w0, w0);
            fma2(p0, wd0, pk2(f0.x, f0.y)); fma2(p1, wd0, pk2(f1.x, f1.y));
        }
        float2 e0 = up2(p0), e1 = up2(p1);
        uint2 hxs = *(const uint2*)(g_xw + (size_t)v * HD + c4);
        float2 xs0 = __half22float2(*(__half2*)&hxs.x);
        float2 xs1 = __half22float2(*(__half2*)&hxs.y);
        float t2 = 2.f * dv * dv;
        float a0 = fmaf(dv, e0.x, fmaf(t2, xs0.x, b4.x));
        float a1 = fmaf(dv, e0.y, fmaf(t2, xs0.y, b4.y));
        float a2 = fmaf(dv, e1.x, fmaf(t2, xs1.x, b4.z));
        float a3 = fmaf(dv, e1.y, fmaf(t2, xs1.y, b4.w));
        *(float4*)(out + (size_t)v * HD + c4) = make_float4(a0, a1, a2, a3);
        ls0 += a0; ls1 += a1; ls2 += a2; ls3 += a3;
        lq0 = fmaf(a0, a0, lq0); lq1 = fmaf(a1, a1, lq1);
        lq2 = fmaf(a2, a2, lq2); lq3 = fmaf(a3, a3, lq3);
    }
    atomicAdd(&s_sum[c4 + 0], ls0); atomicAdd(&s_sum[c4 + 1], ls1);
    atomicAdd(&s_sum[c4 + 2], ls2); atomicAdd(&s_sum[c4 + 3], ls3);
    atomicAdd(&s_sq[c4 + 0], lq0);  atomicAdd(&s_sq[c4 + 1], lq1);
    atomicAdd(&s_sq[c4 + 2], lq2);  atomicAdd(&s_sq[c4 + 3], lq3);
    __syncthreads();
    if (tid < 128) {
        atomicAdd(&g_stats[layer][tid], s_sum[tid]);
        atomicAdd(&g_stats[layer][128 + tid], s_sq[tid]);
    }
    __threadfence();
    __syncthreads();
    if (tid == 0) {
        int p = atomicAdd(&g_done[layer], 1);
        s_last = (p == (int)gridDim.x - 1);
    }
    __syncthreads();
    if (s_last && tid < 128) {
        __threadfence();
        float sum = g_stats[layer][tid];
        float sq  = g_stats[layer][tid + 128];
        g_stats[layer][tid] = 0.f;
        g_stats[layer][tid + 128] = 0.f;
        if (tid == 0) g_done[layer] = 0;
        float inv_n = 1.0f / (float)n;
        float mean = sum * inv_n;
        float var  = fmaxf(sq * inv_n - mean * mean, 0.f);
        float s = bn_g[layer * HD + tid] * rsqrtf(var + 1e-5f);
        g_scale[layer][tid] = s;
        g_sbias[layer][tid] = bn_b[layer * HD + tid] - mean * s;
    }
}

// ---------------------------------------------------------------------------
// Final head: T = relu_bn(g_agg[NLAY-1]) @ fc_w[NLAY]  (K=128 only),
// out = log_softmax(g_out + T + sum_bias). Single-pass tf32. (unchanged)
__global__ __launch_bounds__(256, 2) void k_final(const float* __restrict__ fw,
                                                  const float* __restrict__ fb,
                                                  float* __restrict__ outp, int n) {
    __shared__ __align__(16) float As[2][256][20];
    __shared__ __align__(16) float Bs[2][16][40];
    __shared__ float bsum[40];
    int tid = threadIdx.x;
    int lane = tid & 31, wid = tid >> 5;
    int g4 = lane >> 2, t4 = lane & 3;
    int wr = wid * 32;
    int row0 = blockIdx.x * 256;
    int gr = row0 + tid;
    bool bldr = (tid < 160);
    int bkr = tid / 10, bnc = (tid % 10) * 4;
    const float* A  = g_agg[NLAY - 1];
    const float* sc = g_scale[NLAY - 1];
    const float* sb = g_sbias[NLAY - 1];

    if (tid < 40) {
        float b = 0.f;
        for (int i = 0; i < NLAY + 1; i++) b += fb[i * CD + tid];
        bsum[tid] = b;
    }

    float acc[2][5][4];
#pragma unroll
    for (int mi = 0; mi < 2; mi++)
#pragma unroll
        for (int ni = 0; ni < 5; ni++)
#pragma unroll
            for (int q = 0; q < 4; q++) acc[mi][ni][q] = 0.f;

    float4 pa[4], pbv;
    auto load_slab = [&](int s) {
        int k0 = s * 16;
#pragma unroll
        for (int h = 0; h < 4; h++) pa[h] = make_float4(0.f, 0.f, 0.f, 0.f);
        if (gr < n) {
#pragma unroll
            for (int h = 0; h < 4; h++)
                pa[h] = *(const float4*)(A + (size_t)gr * HD + k0 + h * 4);
        }
#pragma unroll
        for (int h = 0; h < 4; h++) {
            int kk = k0 + h * 4;
            float* p = (float*)&pa[h];
            p[0] = fmaxf(fmaf(p[0], sc[kk + 0], sb[kk + 0]), 0.f);
            p[1] = fmaxf(fmaf(p[1], sc[kk + 1], sb[kk + 1]), 0.f);
            p[2] = fmaxf(fmaf(p[2], sc[kk + 2], sb[kk + 2]), 0.f);
            p[3] = fmaxf(fmaf(p[3], sc[kk + 3], sb[kk + 3]), 0.f);
        }
        if (bldr)
            pbv = *(const float4*)(fw + ((size_t)NLAY * HD + k0 + bkr) * CD + bnc);
    };
    auto store_slab = [&](int buf) {
#pragma unroll
        for (int h = 0; h < 4; h++) *(float4*)&As[buf][tid][h * 4] = pa[h];
        if (bldr) *(float4*)&Bs[buf][bkr][bnc] = pbv;
    };

    load_slab(0);
    store_slab(0);
    __syncthreads();

#pragma unroll
    for (int slab = 0; slab < 8; slab++) {
        int buf = slab & 1;
        if (slab < 7) load_slab(slab + 1);
#pragma unroll
        for (int kk = 0; kk < 2; kk++) {
            int kb = kk * 8;
            unsigned ahi[2][4], bhi[5][2];
#pragma unroll
            for (int mi = 0; mi < 2; mi++) {
                int m0 = wr + mi * 16 + g4;
                ahi[mi][0] = tf32_cvt(As[buf][m0][kb + t4]);
                ahi[mi][1] = tf32_cvt(As[buf][m0 + 8][kb + t4]);
                ahi[mi][2] = tf32_cvt(As[buf][m0][kb + 4 + t4]);
                ahi[mi][3] = tf32_cvt(As[buf][m0 + 8][kb + 4 + t4]);
            }
#pragma unroll
            for (int ni = 0; ni < 5; ni++) {
                int nn = ni * 8 + g4;
                bhi[ni][0] = tf32_cvt(Bs[buf][kb + t4][nn]);
                bhi[ni][1] = tf32_cvt(Bs[buf][kb + 4 + t4][nn]);
            }
#pragma unroll
            for (int mi = 0; mi < 2; mi++)
#pragma unroll
                for (int ni = 0; ni < 5; ni++)
                    mma_tf32(acc[mi][ni], ahi[mi], bhi[ni]);
        }
        if (slab < 7) {
            store_slab(buf ^ 1);
            __syncthreads();
        }
    }

    // epilogue: add g_out + bias, per-row log_softmax (quad shfl), write d_out
#pragma unroll
    for (int mi = 0; mi < 2; mi++) {
#pragma unroll
        for (int half = 0; half < 2; half++) {
            int r = row0 + wr + mi * 16 + half * 8 + g4;
            float v[5][2];
#pragma unroll
            for (int ni = 0; ni < 5; ni++) {
                int c = ni * 8 + t4 * 2;
                float2 o = make_float2(0.f, 0.f);
                if (r < n) o = *(const float2*)(g_out + (size_t)r * CD + c);
                v[ni][0] = acc[mi][ni][half * 2 + 0] + o.x + bsum[c];
                v[ni][1] = acc[mi][ni][half * 2 + 1] + o.y + bsum[c + 1];
            }
            float mx = v[0][0];
#pragma unroll
            for (int ni = 0; ni < 5; ni++) {
                mx = fmaxf(mx, v[ni][0]);
                mx = fmaxf(mx, v[ni][1]);
            }
            mx = fmaxf(mx, __shfl_xor_sync(0xffffffffu, mx, 1));
            mx = fmaxf(mx, __shfl_xor_sync(0xffffffffu, mx, 2));
            float s = 0.f;
#pragma unroll
            for (int ni = 0; ni < 5; ni++)
                s += expf(v[ni][0] - mx) + expf(v[ni][1] - mx);
            s += __shfl_xor_sync(0xffffffffu, s, 1);
            s += __shfl_xor_sync(0xffffffffu, s, 2);
            float ls = mx + logf(s);
            if (r < n) {
#pragma unroll
                for (int ni = 0; ni < 5; ni++)
                    *(float2*)(outp + (size_t)r * CD + ni * 8 + t4 * 2) =
                        make_float2(v[ni][0] - ls, v[ni][1] - ls);
            }
        }
    }
}

// ---------------------------------------------------------------------------
extern "C" void kernel_launch(void* const* d_in, const int* in_sizes, int n_in,
                              void* d_out, int out_size) {
    const float* x      = (const float*)d_in[0];
    const int*   ei     = (const int*)d_in[1];
    const float* conv_w = (const float*)d_in[2];
    const float* conv_b = (const float*)d_in[3];
    const float* bn_g   = (const float*)d_in[4];
    const float* bn_b   = (const float*)d_in[5];
    const float* fc_w   = (const float*)d_in[6];
    const float* fc_b   = (const float*)d_in[7];
    int n = in_sizes[0] / FD;
    int e = in_sizes[1] / 2;
    const int* src = ei;
    const int* dst = ei + e;

    k_hist<<<(e + 255) / 256, 256>>>(dst, e);
    k_scan<<<1, 1024>>>(n);
    k_fill<<<(e + 255) / 256, 256>>>(src, dst, e);

    int gblocks = (n + 127) / 128;
    for (int l = 0; l < NLAY; l++) {
        k_gemm<<<gblocks, 512>>>(x, conv_w + (size_t)l * FD * HD, fc_w, l, n);
        k_agg<<<1184, 256>>>(l, conv_b + (size_t)l * HD, bn_g, bn_b, n);
    }
    k_final<<<(n + 255) / 256, 256>>>(fc_w, fc_b, (float*)d_out, n);
}

// round 12
// speedup vs baseline: 1.1040x; 1.1040x over previous
#include <cuda_runtime.h>
#include <cuda_fp16.h>
#include <math.h>

#define NMAX 100000
#define EMAX 1600000
#define FD 128
#define HD 128
#define CD 40
#define NLAY 4

// ---- static device scratch ----
// Invariant: g_cnt, g_stats, g_done are zero at entry of every kernel_launch
// call (zero at module load; each call re-zeroes them after use).
__device__ __half g_xw[(size_t)NMAX * HD];     // fp16: halves gather L2 traffic
__device__ float g_agg[NLAY][(size_t)NMAX * HD];
__device__ float g_out[(size_t)NMAX * CD];     // running sum of class heads
__device__ int   g_cnt[NMAX];
__device__ float g_dinv[NMAX];
__device__ int   g_off[NMAX + 1];
__device__ int   g_cur[NMAX];
__device__ int   g_csrc[EMAX];
__device__ float g_cval[EMAX];
__device__ float g_stats[NLAY][2 * HD];
__device__ float g_scale[NLAY][HD];
__device__ float g_sbias[NLAY][HD];
__device__ int   g_done[NLAY];

// ---- packed f32x2 helpers ----
__device__ __forceinline__ unsigned long long pk2(float lo, float hi) {
    unsigned long long r;
    asm("mov.b64 %0, {%1, %2};" : "=l"(r) : "f"(lo), "f"(hi));
    return r;
}
__device__ __forceinline__ void fma2(unsigned long long& d,
                                     unsigned long long a, unsigned long long b) {
    asm("fma.rn.f32x2 %0, %1, %2, %0;" : "+l"(d) : "l"(a), "l"(b));
}
__device__ __forceinline__ float2 up2(unsigned long long v) {
    float2 r;
    asm("mov.b64 {%0, %1}, %2;" : "=f"(r.x), "=f"(r.y) : "l"(v));
    return r;
}

// ---- tf32 helpers ----
__device__ __forceinline__ unsigned tf32_cvt(float f) {
    unsigned r;
    asm("cvt.rna.tf32.f32 %0, %1;" : "=r"(r) : "f"(f));
    return r;
}
__device__ __forceinline__ void mma_tf32(float* c, const unsigned* a, const unsigned* b) {
    asm("mma.sync.aligned.m16n8k8.row.col.f32.tf32.tf32.f32 "
        "{%0,%1,%2,%3}, {%4,%5,%6,%7}, {%8,%9}, {%0,%1,%2,%3};"
        : "+f"(c[0]), "+f"(c[1]), "+f"(c[2]), "+f"(c[3])
        : "r"(a[0]), "r"(a[1]), "r"(a[2]), "r"(a[3]), "r"(b[0]), "r"(b[1]));
}

// ---------------------------------------------------------------------------
__global__ void k_hist(const int* __restrict__ dst, int e) {
    int i = blockIdx.x * blockDim.x + threadIdx.x;
    if (i < e) atomicAdd(&g_cnt[dst[i]], 1);
}

__global__ void k_scan(int n) {
    __shared__ int sp[1024];
    int t = threadIdx.x;
    int chunk = (n + 1023) >> 10;
    int beg = t * chunk;
    int end = min(beg + chunk, n);
    int s = 0;
    for (int j = beg; j < end; j++) s += g_cnt[j];
    sp[t] = s;
    __syncthreads();
    for (int d = 1; d < 1024; d <<= 1) {
        int tmp = (t >= d) ? sp[t - d] : 0;
        __syncthreads();
        sp[t] += tmp;
        __syncthreads();
    }
    int base = sp[t] - s;
    for (int j = beg; j < end; j++) {
        int c = g_cnt[j];
        g_cnt[j] = 0;  // self-reset
        g_off[j] = base;
        g_cur[j] = base;
        g_dinv[j] = rsqrtf((float)c + 2.0f);
        base += c;
    }
    if (end == n) g_off[n] = base;
}

__global__ void k_fill(const int* __restrict__ src, const int* __restrict__ dst, int e) {
    int i = blockIdx.x * blockDim.x + threadIdx.x;
    if (i < e) {
        int d = dst[i];
        int s = src[i];
        int p = atomicAdd(&g_cur[d], 1);
        g_csrc[p] = s;
        g_cval[p] = g_dinv[s];
    }
}

// ---------------------------------------------------------------------------
// Conv SGEMM (tf32 3-pass) FUSED with per-layer class head (tf32 1-pass):
//   g_xw (fp16) = A @ conv_w[layer]      (A = outs[layer], BN+ReLU on load)
//   g_out (+)= A @ fc_w[layer]           (head reuses smem A tile + ahi frags)
__global__ __launch_bounds__(512, 1) void k_gemm(const float* __restrict__ x,
                                                 const float* __restrict__ W,
                                                 const float* __restrict__ fw,
                                                 int layer, int n) {
    __shared__ __align__(16) float As[2][128][20];
    __shared__ __align__(16) float Bs[2][16][136];
    __shared__ __align__(16) float Bh[2][16][40];
    const float* A  = (layer == 0) ? x : g_agg[layer - 1];
    const float* sc = (layer > 0) ? g_scale[layer - 1] : 0;
    const float* sb = (layer > 0) ? g_sbias[layer - 1] : 0;
    int tid = threadIdx.x;
    int lane = tid & 31, wid = tid >> 5;
    int g4 = lane >> 2, t4 = lane & 3;
    int wr = (wid >> 2) * 32, wc = (wid & 3) * 32;
    int hc = wid & 3;
    int ar = tid >> 2, akq = (tid & 3) * 4;
    int bk = tid >> 5, bn0 = (tid & 31) * 4;
    bool hldr = (tid < 160);
    int hkr = tid / 10, hnc = (tid % 10) * 4;
    int row0 = blockIdx.x * 128;
    int gr = row0 + ar;

    float acc[2][4][4];
#pragma unroll
    for (int mi = 0; mi < 2; mi++)
#pragma unroll
        for (int ni = 0; ni < 4; ni++)
#pragma unroll
            for (int q = 0; q < 4; q++) acc[mi][ni][q] = 0.f;
    float acch[2][2][4];
#pragma unroll
    for (int s = 0; s < 2; s++)
#pragma unroll
        for (int mi = 0; mi < 2; mi++)
#pragma unroll
            for (int q = 0; q < 4; q++) acch[s][mi][q] = 0.f;

    float4 pa, pb, ph;
    auto load_slab = [&](int s) {
        int k0 = s * 16;
        pa = make_float4(0.f, 0.f, 0.f, 0.f);
        if (gr < n) pa = *(const float4*)(A + (size_t)gr * HD + k0 + akq);
        if (layer > 0) {
            int kb = k0 + akq;
            pa.x = fmaxf(fmaf(pa.x, sc[kb + 0], sb[kb + 0]), 0.f);
            pa.y = fmaxf(fmaf(pa.y, sc[kb + 1], sb[kb + 1]), 0.f);
            pa.z = fmaxf(fmaf(pa.z, sc[kb + 2], sb[kb + 2]), 0.f);
            pa.w = fmaxf(fmaf(pa.w, sc[kb + 3], sb[kb + 3]), 0.f);
        }
        pb = *(const float4*)(W + (size_t)(k0 + bk) * HD + bn0);
        if (hldr)
            ph = *(const float4*)(fw + ((size_t)layer * HD + k0 + hkr) * CD + hnc);
    };
    auto store_slab = [&](int buf) {
        *(float4*)&As[buf][ar][akq] = pa;
        *(float4*)&Bs[buf][bk][bn0] = pb;
        if (hldr) *(float4*)&Bh[buf][hkr][hnc] = ph;
    };

    load_slab(0);
    store_slab(0);
    __syncthreads();

#pragma unroll
    for (int ks = 0; ks < 8; ks++) {
        int buf = ks & 1;
        if (ks < 7) load_slab(ks + 1);
#pragma unroll
        for (int kk = 0; kk < 2; kk++) {
            int kb = kk * 8;
            float af[2][4], bf[4][2];
#pragma unroll
            for (int mi = 0; mi < 2; mi++) {
                int m0 = wr + mi * 16 + g4;
                af[mi][0] = As[buf][m0][kb + t4];
                af[mi][1] = As[buf][m0 + 8][kb + t4];
                af[mi][2] = As[buf][m0][kb + 4 + t4];
                af[mi][3] = As[buf][m0 + 8][kb + 4 + t4];
            }
#pragma unroll
            for (int ni = 0; ni < 4; ni++) {
                int nn = wc + ni * 8 + g4;
                bf[ni][0] = Bs[buf][kb + t4][nn];
                bf[ni][1] = Bs[buf][kb + 4 + t4][nn];
            }
            unsigned ahi[2][4], bhi[4][2];
#pragma unroll
            for (int mi = 0; mi < 2; mi++)
#pragma unroll
                for (int q = 0; q < 4; q++) ahi[mi][q] = tf32_cvt(af[mi][q]);
#pragma unroll
            for (int ni = 0; ni < 4; ni++) {
                bhi[ni][0] = tf32_cvt(bf[ni][0]);
                bhi[ni][1] = tf32_cvt(bf[ni][1]);
            }
#pragma unroll
            for (int mi = 0; mi < 2; mi++)
#pragma unroll
                for (int ni = 0; ni < 4; ni++)
                    mma_tf32(acc[mi][ni], ahi[mi], bhi[ni]);
            unsigned blo[4][2];
#pragma unroll
            for (int ni = 0; ni < 4; ni++) {
                blo[ni][0] = tf32_cvt(bf[ni][0] - __uint_as_float(bhi[ni][0]));
                blo[ni][1] = tf32_cvt(bf[ni][1] - __uint_as_float(bhi[ni][1]));
            }
#pragma unroll
            for (int mi = 0; mi < 2; mi++)
#pragma unroll
                for (int ni = 0; ni < 4; ni++)
                    mma_tf32(acc[mi][ni], ahi[mi], blo[ni]);
            unsigned alo[2][4];
#pragma unroll
            for (int mi = 0; mi < 2; mi++)
#pragma unroll
                for (int q = 0; q < 4; q++)
                    alo[mi][q] = tf32_cvt(af[mi][q] - __uint_as_float(ahi[mi][q]));
#pragma unroll
            for (int mi = 0; mi < 2; mi++)
#pragma unroll
                for (int ni = 0; ni < 4; ni++)
                    mma_tf32(acc[mi][ni], alo[mi], bhi[ni]);
            // ---- head (single-pass tf32, reuses ahi) ----
            {
                unsigned hb[2];
                int nn = hc * 8 + g4;
                hb[0] = tf32_cvt(Bh[buf][kb + t4][nn]);
                hb[1] = tf32_cvt(Bh[buf][kb + 4 + t4][nn]);
#pragma unroll
                for (int mi = 0; mi < 2; mi++)
                    mma_tf32(acch[0][mi], ahi[mi], hb);
                if (hc == 3) {
                    unsigned hb4[2];
                    int nn4 = 32 + g4;
                    hb4[0] = tf32_cvt(Bh[buf][kb + t4][nn4]);
                    hb4[1] = tf32_cvt(Bh[buf][kb + 4 + t4][nn4]);
#pragma unroll
                    for (int mi = 0; mi < 2; mi++)
                        mma_tf32(acch[1][mi], ahi[mi], hb4);
                }
            }
        }
        if (ks < 7) {
            store_slab(buf ^ 1);
            __syncthreads();
        }
    }
    // conv epilogue: write fp16 (half2 per 2 cols)
#pragma unroll
    for (int mi = 0; mi < 2; mi++) {
#pragma unroll
        for (int ni = 0; ni < 4; ni++) {
            int r = row0 + wr + mi * 16 + g4;
            int c = wc + ni * 8 + t4 * 2;
            if (r < n)
                *(__half2*)(g_xw + (size_t)r * HD + c) =
                    __floats2half2_rn(acc[mi][ni][0], acc[mi][ni][1]);
            if (r + 8 < n)
                *(__half2*)(g_xw + (size_t)(r + 8) * HD + c) =
                    __floats2half2_rn(acc[mi][ni][2], acc[mi][ni][3]);
        }
    }
    // head epilogue: unique (row, tile) ownership -> plain RMW, no atomics
    int nslots = (hc == 3) ? 2 : 1;
    for (int s = 0; s < nslots; s++) {
        int tile = (s == 0) ? hc : 4;
        int c = tile * 8 + t4 * 2;
#pragma unroll
        for (int mi = 0; mi < 2; mi++) {
#pragma unroll
            for (int half = 0; half < 2; half++) {
                int r = row0 + wr + mi * 16 + half * 8 + g4;
                if (r < n) {
                    float2 val = make_float2(acch[s][mi][half * 2 + 0],
                                             acch[s][mi][half * 2 + 1]);
                    float2* p = (float2*)(g_out + (size_t)r * CD + c);
                    if (layer == 0) {
                        *p = val;
                    } else {
                        float2 o = *p;
                        *p = make_float2(o.x + val.x, o.y + val.y);
                    }
                }
            }
        }
    }
}

// ---------------------------------------------------------------------------
// Aggregation: warp per node; lane owns 4 columns; unroll-8 fp16 gather,
// fp32 accumulate. BN stats + fused scale/bias in last block.
__global__ __launch_bounds__(256) void k_agg(int layer, const float* __restrict__ convb,
                                             const float* __restrict__ bn_g,
                                             const float* __restrict__ bn_b, int n) {
    __shared__ float s_sum[128], s_sq[128];
    __shared__ int s_last;
    int tid = threadIdx.x;
    if (tid < 128) { s_sum[tid] = 0.f; s_sq[tid] = 0.f; }
    __syncthreads();

    int lane = tid & 31;
    int warp = tid >> 5;
    int c4 = lane * 4;
    float4 b4 = *(const float4*)(convb + c4);
    float* out = g_agg[layer];

    int gw = blockIdx.x * 8 + warp;
    int nw = gridDim.x * 8;

    float ls0 = 0.f, ls1 = 0.f, ls2 = 0.f, ls3 = 0.f;
    float lq0 = 0.f, lq1 = 0.f, lq2 = 0.f, lq3 = 0.f;

    for (int v = gw; v < n; v += nw) {
        int r0 = g_off[v], r1 = g_off[v + 1];
        float dv = g_dinv[v];
        unsigned long long p0 = 0ull, p1 = 0ull;
        int j = r0;
        for (; j + 7 < r1; j += 8) {
            int   si[8];
            float wi[8];
#pragma unroll
            for (int u = 0; u < 8; u++) { si[u] = g_csrc[j + u]; wi[u] = g_cval[j + u]; }
            uint2 hx[8];
#pragma unroll
            for (int u = 0; u < 8; u++)
                hx[u] = *(const uint2*)(g_xw + (size_t)si[u] * HD + c4);
#pragma unroll
            for (int u = 0; u < 8; u++) {
                float2 f0 = __half22float2(*(__half2*)&hx[u].x);
                float2 f1 = __half22float2(*(__half2*)&hx[u].y);
                unsigned long long wd = pk2(wi[u], wi[u]);
                fma2(p0, wd, pk2(f0.x, f0.y));
                fma2(p1, wd, pk2(f1.x, f1.y));
            }
        }
        for (; j < r1; j++) {
            int s0 = g_csrc[j];
            float w0 = g_cval[j];
            uint2 hx = *(const uint2*)(g_xw + (size_t)s0 * HD + c4);
            float2 f0 = __half22float2(*(__half2*)&hx.x);
            float2 f1 = __half22float2(*(__half2*)&hx.y);
            unsigned long long wd0 = pk2(w0, w0);
            fma2(p0, wd0, pk2(f0.x, f0.y)); fma2(p1, wd0, pk2(f1.x, f1.y));
        }
        float2 e0 = up2(p0), e1 = up2(p1);
        uint2 hxs = *(const uint2*)(g_xw + (size_t)v * HD + c4);
        float2 xs0 = __half22float2(*(__half2*)&hxs.x);
        float2 xs1 = __half22float2(*(__half2*)&hxs.y);
        float t2 = 2.f * dv * dv;
        float a0 = fmaf(dv, e0.x, fmaf(t2, xs0.x, b4.x));
        float a1 = fmaf(dv, e0.y, fmaf(t2, xs0.y, b4.y));
        float a2 = fmaf(dv, e1.x, fmaf(t2, xs1.x, b4.z));
        float a3 = fmaf(dv, e1.y, fmaf(t2, xs1.y, b4.w));
        *(float4*)(out + (size_t)v * HD + c4) = make_float4(a0, a1, a2, a3);
        ls0 += a0; ls1 += a1; ls2 += a2; ls3 += a3;
        lq0 = fmaf(a0, a0, lq0); lq1 = fmaf(a1, a1, lq1);
        lq2 = fmaf(a2, a2, lq2); lq3 = fmaf(a3, a3, lq3);
    }
    atomicAdd(&s_sum[c4 + 0], ls0); atomicAdd(&s_sum[c4 + 1], ls1);
    atomicAdd(&s_sum[c4 + 2], ls2); atomicAdd(&s_sum[c4 + 3], ls3);
    atomicAdd(&s_sq[c4 + 0], lq0);  atomicAdd(&s_sq[c4 + 1], lq1);
    atomicAdd(&s_sq[c4 + 2], lq2);  atomicAdd(&s_sq[c4 + 3], lq3);
    __syncthreads();
    if (tid < 128) {
        atomicAdd(&g_stats[layer][tid], s_sum[tid]);
        atomicAdd(&g_stats[layer][128 + tid], s_sq[tid]);
    }
    __threadfence();
    __syncthreads();
    if (tid == 0) {
        int p = atomicAdd(&g_done[layer], 1);
        s_last = (p == (int)gridDim.x - 1);
    }
    __syncthreads();
    if (s_last && tid < 128) {
        __threadfence();
        float sum = g_stats[layer][tid];
        float sq  = g_stats[layer][tid + 128];
        g_stats[layer][tid] = 0.f;
        g_stats[layer][tid + 128] = 0.f;
        if (tid == 0) g_done[layer] = 0;
        float inv_n = 1.0f / (float)n;
        float mean = sum * inv_n;
        float var  = fmaxf(sq * inv_n - mean * mean, 0.f);
        float s = bn_g[layer * HD + tid] * rsqrtf(var + 1e-5f);
        g_scale[layer][tid] = s;
        g_sbias[layer][tid] = bn_b[layer * HD + tid] - mean * s;
    }
}

// ---------------------------------------------------------------------------
// Final head: T = relu_bn(g_agg[NLAY-1]) @ fc_w[NLAY]  (K=128 only),
// out = log_softmax(g_out + T + sum_bias). Single-pass tf32.
__global__ __launch_bounds__(256, 2) void k_final(const float* __restrict__ fw,
                                                  const float* __restrict__ fb,
                                                  float* __restrict__ outp, int n) {
    __shared__ __align__(16) float As[2][256][20];
    __shared__ __align__(16) float Bs[2][16][40];
    __shared__ float bsum[40];
    int tid = threadIdx.x;
    int lane = tid & 31, wid = tid >> 5;
    int g4 = lane >> 2, t4 = lane & 3;
    int wr = wid * 32;
    int row0 = blockIdx.x * 256;
    int gr = row0 + tid;
    bool bldr = (tid < 160);
    int bkr = tid / 10, bnc = (tid % 10) * 4;
    const float* A  = g_agg[NLAY - 1];
    const float* sc = g_scale[NLAY - 1];
    const float* sb = g_sbias[NLAY - 1];

    if (tid < 40) {
        float b = 0.f;
        for (int i = 0; i < NLAY + 1; i++) b += fb[i * CD + tid];
        bsum[tid] = b;
    }

    float acc[2][5][4];
#pragma unroll
    for (int mi = 0; mi < 2; mi++)
#pragma unroll
        for (int ni = 0; ni < 5; ni++)
#pragma unroll
            for (int q = 0; q < 4; q++) acc[mi][ni][q] = 0.f;

    float4 pa[4], pbv;
    auto load_slab = [&](int s) {
        int k0 = s * 16;
#pragma unroll
        for (int h = 0; h < 4; h++) pa[h] = make_float4(0.f, 0.f, 0.f, 0.f);
        if (gr < n) {
#pragma unroll
            for (int h = 0; h < 4; h++)
                pa[h] = *(const float4*)(A + (size_t)gr * HD + k0 + h * 4);
        }
#pragma unroll
        for (int h = 0; h < 4; h++) {
            int kk = k0 + h * 4;
            float* p = (float*)&pa[h];
            p[0] = fmaxf(fmaf(p[0], sc[kk + 0], sb[kk + 0]), 0.f);
            p[1] = fmaxf(fmaf(p[1], sc[kk + 1], sb[kk + 1]), 0.f);
            p[2] = fmaxf(fmaf(p[2], sc[kk + 2], sb[kk + 2]), 0.f);
            p[3] = fmaxf(fmaf(p[3], sc[kk + 3], sb[kk + 3]), 0.f);
        }
        if (bldr)
            pbv = *(const float4*)(fw + ((size_t)NLAY * HD + k0 + bkr) * CD + bnc);
    };
    auto store_slab = [&](int buf) {
#pragma unroll
        for (int h = 0; h < 4; h++) *(float4*)&As[buf][tid][h * 4] = pa[h];
        if (bldr) *(float4*)&Bs[buf][bkr][bnc] = pbv;
    };

    load_slab(0);
    store_slab(0);
    __syncthreads();

#pragma unroll
    for (int slab = 0; slab < 8; slab++) {
        int buf = slab & 1;
        if (slab < 7) load_slab(slab + 1);
#pragma unroll
        for (int kk = 0; kk < 2; kk++) {
            int kb = kk * 8;
            unsigned ahi[2][4], bhi[5][2];
#pragma unroll
            for (int mi = 0; mi < 2; mi++) {
                int m0 = wr + mi * 16 + g4;
                ahi[mi][0] = tf32_cvt(As[buf][m0][kb + t4]);
                ahi[mi][1] = tf32_cvt(As[buf][m0 + 8][kb + t4]);
                ahi[mi][2] = tf32_cvt(As[buf][m0][kb + 4 + t4]);
                ahi[mi][3] = tf32_cvt(As[buf][m0 + 8][kb + 4 + t4]);
            }
#pragma unroll
            for (int ni = 0; ni < 5; ni++) {
                int nn = ni * 8 + g4;
                bhi[ni][0] = tf32_cvt(Bs[buf][kb + t4][nn]);
                bhi[ni][1] = tf32_cvt(Bs[buf][kb + 4 + t4][nn]);
            }
#pragma unroll
            for (int mi = 0; mi < 2; mi++)
#pragma unroll
                for (int ni = 0; ni < 5; ni++)
                    mma_tf32(acc[mi][ni], ahi[mi], bhi[ni]);
        }
        if (slab < 7) {
            store_slab(buf ^ 1);
            __syncthreads();
        }
    }

    // epilogue: add g_out + bias, per-row log_softmax (quad shfl), write d_out
#pragma unroll
    for (int mi = 0; mi < 2; mi++) {
#pragma unroll
        for (int half = 0; half < 2; half++) {
            int r = row0 + wr + mi * 16 + half * 8 + g4;
            float v[5][2];
#pragma unroll
            for (int ni = 0; ni < 5; ni++) {
                int c = ni * 8 + t4 * 2;
                float2 o = make_float2(0.f, 0.f);
                if (r < n) o = *(const float2*)(g_out + (size_t)r * CD + c);
                v[ni][0] = acc[mi][ni][half * 2 + 0] + o.x + bsum[c];
                v[ni][1] = acc[mi][ni][half * 2 + 1] + o.y + bsum[c + 1];
            }
            float mx = v[0][0];
#pragma unroll
            for (int ni = 0; ni < 5; ni++) {
                mx = fmaxf(mx, v[ni][0]);
                mx = fmaxf(mx, v[ni][1]);
            }
            mx = fmaxf(mx, __shfl_xor_sync(0xffffffffu, mx, 1));
            mx = fmaxf(mx, __shfl_xor_sync(0xffffffffu, mx, 2));
            float s = 0.f;
#pragma unroll
            for (int ni = 0; ni < 5; ni++)
                s += expf(v[ni][0] - mx) + expf(v[ni][1] - mx);
            s += __shfl_xor_sync(0xffffffffu, s, 1);
            s += __shfl_xor_sync(0xffffffffu, s, 2);
            float ls = mx + logf(s);
            if (r < n) {
#pragma unroll
                for (int ni = 0; ni < 5; ni++)
                    *(float2*)(outp + (size_t)r * CD + ni * 8 + t4 * 2) =
                        make_float2(v[ni][0] - ls, v[ni][1] - ls);
            }
        }
    }
}

// ---------------------------------------------------------------------------
// Side stream + events for overlapping the graph-prep chain with gemm layer 0.
// Created once on first call (the uncaptured correctness run); no device
// memory is allocated. Cross-stream event edges are graph-capturable.
static cudaStream_t g_s2 = 0;
static cudaEvent_t  g_ev_fork = 0, g_ev_join = 0;

extern "C" void kernel_launch(void* const* d_in, const int* in_sizes, int n_in,
                              void* d_out, int out_size) {
    const float* x      = (const float*)d_in[0];
    const int*   ei     = (const int*)d_in[1];
    const float* conv_w = (const float*)d_in[2];
    const float* conv_b = (const float*)d_in[3];
    const float* bn_g   = (const float*)d_in[4];
    const float* bn_b   = (const float*)d_in[5];
    const float* fc_w   = (const float*)d_in[6];
    const float* fc_b   = (const float*)d_in[7];
    int n = in_sizes[0] / FD;
    int e = in_sizes[1] / 2;
    const int* src = ei;
    const int* dst = ei + e;

    if (g_s2 == 0) {
        cudaStreamCreateWithFlags(&g_s2, cudaStreamNonBlocking);
        cudaEventCreateWithFlags(&g_ev_fork, cudaEventDisableTiming);
        cudaEventCreateWithFlags(&g_ev_join, cudaEventDisableTiming);
    }

    int gblocks = (n + 127) / 128;

    // fork: graph prep (hist -> scan -> fill) on side stream,
    // concurrent with layer-0 GEMM + head on the main stream.
    cudaEventRecord(g_ev_fork, 0);
    cudaStreamWaitEvent(g_s2, g_ev_fork, 0);
    k_hist<<<(e + 255) / 256, 256, 0, g_s2>>>(dst, e);
    k_scan<<<1, 1024, 0, g_s2>>>(n);
    k_fill<<<(e + 255) / 256, 256, 0, g_s2>>>(src, dst, e);
    cudaEventRecord(g_ev_join, g_s2);

    k_gemm<<<gblocks, 512>>>(x, conv_w, fc_w, 0, n);

    // join: aggregation needs both gemm0 (main) and CSR (side)
    cudaStreamWaitEvent(0, g_ev_join, 0);
    k_agg<<<1184, 256>>>(0, conv_b, bn_g, bn_b, n);

    for (int l = 1; l < NLAY; l++) {
        k_gemm<<<gblocks, 512>>>(x, conv_w + (size_t)l * FD * HD, fc_w, l, n);
        k_agg<<<1184, 256>>>(l, conv_b + (size_t)l * HD, bn_g, bn_b, n);
    }
    k_final<<<(n + 255) / 256, 256>>>(fc_w, fc_b, (float*)d_out, n);
}

// round 14
// speedup vs baseline: 1.2347x; 1.1184x over previous
#include <cuda_runtime.h>
#include <cuda_fp16.h>
#include <math.h>

#define NMAX 100000
#define EMAX 1600000
#define FD 128
#define HD 128
#define CD 40
#define NLAY 4

// ---- static device scratch ----
// Invariant: g_cnt, g_stats, g_done are zero at entry of every kernel_launch
// call (zero at module load; each call re-zeroes them after use).
__device__ __half g_xw[(size_t)NMAX * HD];     // fp16: halves gather L2 traffic
__device__ float g_agg[NLAY][(size_t)NMAX * HD];
__device__ float g_out[(size_t)NMAX * CD];     // running sum of class heads
__device__ int   g_cnt[NMAX];
__device__ float g_dinv[NMAX];
__device__ int   g_off[NMAX + 1];
__device__ int   g_cur[NMAX];
__device__ int   g_csrc[EMAX];
__device__ float g_cval[EMAX];
__device__ float g_stats[NLAY][2 * HD];
__device__ float g_scale[NLAY][HD];
__device__ float g_sbias[NLAY][HD];
__device__ int   g_done[NLAY];

// ---- packed f32x2 helpers ----
__device__ __forceinline__ unsigned long long pk2(float lo, float hi) {
    unsigned long long r;
    asm("mov.b64 %0, {%1, %2};" : "=l"(r) : "f"(lo), "f"(hi));
    return r;
}
__device__ __forceinline__ void fma2(unsigned long long& d,
                                     unsigned long long a, unsigned long long b) {
    asm("fma.rn.f32x2 %0, %1, %2, %0;" : "+l"(d) : "l"(a), "l"(b));
}
__device__ __forceinline__ float2 up2(unsigned long long v) {
    float2 r;
    asm("mov.b64 {%0, %1}, %2;" : "=f"(r.x), "=f"(r.y) : "l"(v));
    return r;
}

// ---- tf32 helpers (k_final) ----
__device__ __forceinline__ unsigned tf32_cvt(float f) {
    unsigned r;
    asm("cvt.rna.tf32.f32 %0, %1;" : "=r"(r) : "f"(f));
    return r;
}
__device__ __forceinline__ void mma_tf32(float* c, const unsigned* a, const unsigned* b) {
    asm("mma.sync.aligned.m16n8k8.row.col.f32.tf32.tf32.f32 "
        "{%0,%1,%2,%3}, {%4,%5,%6,%7}, {%8,%9}, {%0,%1,%2,%3};"
        : "+f"(c[0]), "+f"(c[1]), "+f"(c[2]), "+f"(c[3])
        : "r"(a[0]), "r"(a[1]), "r"(a[2]), "r"(a[3]), "r"(b[0]), "r"(b[1]));
}

// ---- fp16 m16n8k16 MMA (fp32 accum) + ldmatrix ----
__device__ __forceinline__ void mma_f16(float* c, const unsigned* a, const unsigned* b) {
    asm("mma.sync.aligned.m16n8k16.row.col.f32.f16.f16.f32 "
        "{%0,%1,%2,%3}, {%4,%5,%6,%7}, {%8,%9}, {%0,%1,%2,%3};"
        : "+f"(c[0]), "+f"(c[1]), "+f"(c[2]), "+f"(c[3])
        : "r"(a[0]), "r"(a[1]), "r"(a[2]), "r"(a[3]), "r"(b[0]), "r"(b[1]));
}
__device__ __forceinline__ void ldsm_x4_t(unsigned& r0, unsigned& r1,
                                          unsigned& r2, unsigned& r3, unsigned addr) {
    asm volatile("ldmatrix.sync.aligned.m8n8.x4.trans.shared.b16 {%0,%1,%2,%3}, [%4];"
                 : "=r"(r0), "=r"(r1), "=r"(r2), "=r"(r3) : "r"(addr));
}
__device__ __forceinline__ void ldsm_x2_t(unsigned& r0, unsigned& r1, unsigned addr) {
    asm volatile("ldmatrix.sync.aligned.m8n8.x2.trans.shared.b16 {%0,%1}, [%2];"
                 : "=r"(r0), "=r"(r1) : "r"(addr));
}

// ---------------------------------------------------------------------------
__global__ void k_hist(const int* __restrict__ dst, int e) {
    int i = blockIdx.x * blockDim.x + threadIdx.x;
    if (i < e) atomicAdd(&g_cnt[dst[i]], 1);
}

__global__ void k_scan(int n) {
    __shared__ int sp[1024];
    int t = threadIdx.x;
    int chunk = (n + 1023) >> 10;
    int beg = t * chunk;
    int end = min(beg + chunk, n);
    int s = 0;
    for (int j = beg; j < end; j++) s += g_cnt[j];
    sp[t] = s;
    __syncthreads();
    for (int d = 1; d < 1024; d <<= 1) {
        int tmp = (t >= d) ? sp[t - d] : 0;
        __syncthreads();
        sp[t] += tmp;
        __syncthreads();
    }
    int base = sp[t] - s;
    for (int j = beg; j < end; j++) {
        int c = g_cnt[j];
        g_cnt[j] = 0;  // self-reset
        g_off[j] = base;
        g_cur[j] = base;
        g_dinv[j] = rsqrtf((float)c + 2.0f);
        base += c;
    }
    if (end == n) g_off[n] = base;
}

__global__ void k_fill(const int* __restrict__ src, const int* __restrict__ dst, int e) {
    int i = blockIdx.x * blockDim.x + threadIdx.x;
    if (i < e) {
        int d = dst[i];
        int s = src[i];
        int p = atomicAdd(&g_cur[d], 1);
        g_csrc[p] = s;
        g_cval[p] = g_dinv[s];
    }
}

// ---------------------------------------------------------------------------
// Conv SGEMM via SPLIT-FP16 m16n8k16 (a=ahi+alo, b=bhi+blo, 3 cross terms)
// fused with class head. B kept in natural [k][n] layout; col-major fragments
// via ldmatrix.x4.trans. Lo block at col 136 (272B: 16B-aligned for ldmatrix).
//   g_xw (fp16) = A @ conv_w[layer];  g_out (+)= A @ fc_w[layer]
__global__ __launch_bounds__(512, 1) void k_gemm(const float* __restrict__ x,
                                                 const float* __restrict__ W,
                                                 const float* __restrict__ fw,
                                                 int layer, int n) {
    // A: [m][k] halves, hi cols 0-15, lo cols 16-31; pitch 40 (conflict-free)
    __shared__ __align__(16) __half As2[2][128][40];
    // B: [k][n] halves, hi cols 0-127, lo cols 136-263; pitch 264
    // (row stride 132 words -> 4k mod 32 distinct; lo offset 272B 16-aligned)
    __shared__ __align__(16) __half Bs2[2][16][264];
    // head B: [k][n] halves, hi only, cols 0-39; pitch 56
    __shared__ __align__(16) __half Hh[2][16][56];
    const float* A  = (layer == 0) ? x : g_agg[layer - 1];
    const float* sc = (layer > 0) ? g_scale[layer - 1] : 0;
    const float* sb = (layer > 0) ? g_sbias[layer - 1] : 0;
    int tid = threadIdx.x;
    int lane = tid & 31, wid = tid >> 5;
    int g4 = lane >> 2, t4 = lane & 3;
    int wr = (wid >> 2) * 32, wc = (wid & 3) * 32;
    int hc = wid & 3;
    int ar = tid >> 2, akq = (tid & 3) * 4;
    int bk = tid >> 5, bn0 = (tid & 31) * 4;
    bool hldr = (tid < 160);
    int hkr = tid / 10, hnc = (tid % 10) * 4;
    int row0 = blockIdx.x * 128;
    int gr = row0 + ar;

    // ldmatrix addressing
    int lt = lane >> 3;               // tile index 0-3
    int lr = lane & 7;                // row within tile
    int ld_k = ((lt & 1) ? 8 : 0) + lr;   // k row
    int ld_n8 = (lt >> 1) * 8;            // n-tile offset (0 or 8)
    unsigned b_sbase = (unsigned)__cvta_generic_to_shared(&Bs2[0][0][0]);
    unsigned h_sbase = (unsigned)__cvta_generic_to_shared(&Hh[0][0][0]);

    float acc[2][4][4];
#pragma unroll
    for (int mi = 0; mi < 2; mi++)
#pragma unroll
        for (int ni = 0; ni < 4; ni++)
#pragma unroll
            for (int q = 0; q < 4; q++) acc[mi][ni][q] = 0.f;
    float acch[2][2][4];
#pragma unroll
    for (int s = 0; s < 2; s++)
#pragma unroll
        for (int mi = 0; mi < 2; mi++)
#pragma unroll
            for (int q = 0; q < 4; q++) acch[s][mi][q] = 0.f;

    float4 pa, pb, ph;
    auto load_slab = [&](int s) {
        int k0 = s * 16;
        pa = make_float4(0.f, 0.f, 0.f, 0.f);
        if (gr < n) pa = *(const float4*)(A + (size_t)gr * HD + k0 + akq);
        if (layer > 0) {
            int kb = k0 + akq;
            pa.x = fmaxf(fmaf(pa.x, sc[kb + 0], sb[kb + 0]), 0.f);
            pa.y = fmaxf(fmaf(pa.y, sc[kb + 1], sb[kb + 1]), 0.f);
            pa.z = fmaxf(fmaf(pa.z, sc[kb + 2], sb[kb + 2]), 0.f);
            pa.w = fmaxf(fmaf(pa.w, sc[kb + 3], sb[kb + 3]), 0.f);
        }
        pb = *(const float4*)(W + (size_t)(k0 + bk) * HD + bn0);
        if (hldr)
            ph = *(const float4*)(fw + ((size_t)layer * HD + k0 + hkr) * CD + hnc);
    };
    auto store_slab = [&](int buf) {
        // A hi/lo split, row-contiguous half2 stores
        float av[4] = {pa.x, pa.y, pa.z, pa.w};
        __half ah4[4], al4[4];
#pragma unroll
        for (int j = 0; j < 4; j++) {
            ah4[j] = __float2half_rn(av[j]);
            al4[j] = __float2half_rn(av[j] - __half2float(ah4[j]));
        }
        *(__half2*)&As2[buf][ar][akq]          = *(__half2*)&ah4[0];
        *(__half2*)&As2[buf][ar][akq + 2]      = *(__half2*)&ah4[2];
        *(__half2*)&As2[buf][ar][16 + akq]     = *(__half2*)&al4[0];
        *(__half2*)&As2[buf][ar][16 + akq + 2] = *(__half2*)&al4[2];
        // B hi/lo split, NATURAL [k][n] layout (vectorized, no scatter)
        float bv[4] = {pb.x, pb.y, pb.z, pb.w};
        __half bh4[4], bl4[4];
#pragma unroll
        for (int j = 0; j < 4; j++) {
            bh4[j] = __float2half_rn(bv[j]);
            bl4[j] = __float2half_rn(bv[j] - __half2float(bh4[j]));
        }
        *(__half2*)&Bs2[buf][bk][bn0]           = *(__half2*)&bh4[0];
        *(__half2*)&Bs2[buf][bk][bn0 + 2]       = *(__half2*)&bh4[2];
        *(__half2*)&Bs2[buf][bk][136 + bn0]     = *(__half2*)&bl4[0];
        *(__half2*)&Bs2[buf][bk][136 + bn0 + 2] = *(__half2*)&bl4[2];
        if (hldr) {
            float hv4[4] = {ph.x, ph.y, ph.z, ph.w};
            __half hh4[4];
#pragma unroll
            for (int j = 0; j < 4; j++) hh4[j] = __float2half_rn(hv4[j]);
            *(__half2*)&Hh[buf][hkr][hnc]     = *(__half2*)&hh4[0];
            *(__half2*)&Hh[buf][hkr][hnc + 2] = *(__half2*)&hh4[2];
        }
    };

    load_slab(0);
    store_slab(0);
    __syncthreads();

#pragma unroll
    for (int ks = 0; ks < 8; ks++) {
        int buf = ks & 1;
        if (ks < 7) load_slab(ks + 1);
        // A fragments: direct LDS.32 (conflict-free pattern)
        unsigned ah[2][4], al[2][4];
#pragma unroll
        for (int mi = 0; mi < 2; mi++) {
            int m = wr + mi * 16 + g4;
            ah[mi][0] = *(const unsigned*)&As2[buf][m][2 * t4];
            ah[mi][1] = *(const unsigned*)&As2[buf][m + 8][2 * t4];
            ah[mi][2] = *(const unsigned*)&As2[buf][m][8 + 2 * t4];
            ah[mi][3] = *(const unsigned*)&As2[buf][m + 8][8 + 2 * t4];
            al[mi][0] = *(const unsigned*)&As2[buf][m][16 + 2 * t4];
            al[mi][1] = *(const unsigned*)&As2[buf][m + 8][16 + 2 * t4];
            al[mi][2] = *(const unsigned*)&As2[buf][m][24 + 2 * t4];
            al[mi][3] = *(const unsigned*)&As2[buf][m + 8][24 + 2 * t4];
        }
        // B fragments via ldmatrix.trans: pairs (ni, ni+1) per x4
        unsigned bh[4][2], bl[4][2];
        unsigned bufoff = (unsigned)buf * 16u * 264u * 2u;
#pragma unroll
        for (int p = 0; p < 2; p++) {
            unsigned addr_hi = b_sbase + bufoff +
                ((unsigned)(ld_k * 264 + wc + p * 16 + ld_n8)) * 2u;
            ldsm_x4_t(bh[2 * p][0], bh[2 * p][1], bh[2 * p + 1][0], bh[2 * p + 1][1], addr_hi);
            ldsm_x4_t(bl[2 * p][0], bl[2 * p][1], bl[2 * p + 1][0], bl[2 * p + 1][1],
                      addr_hi + 136u * 2u);
        }
        // conv: 3 cross terms
#pragma unroll
        for (int mi = 0; mi < 2; mi++)
#pragma unroll
            for (int ni = 0; ni < 4; ni++) {
                mma_f16(acc[mi][ni], ah[mi], bh[ni]);
                mma_f16(acc[mi][ni], ah[mi], bl[ni]);
                mma_f16(acc[mi][ni], al[mi], bh[ni]);
            }
        // head: (ahi+alo) x bhi via ldmatrix.x2.trans
        {
            unsigned hbuf = (unsigned)buf * 16u * 56u * 2u;
            unsigned hb[2];
            unsigned haddr = h_sbase + hbuf +
                ((unsigned)(((lane & 7) + ((lt & 1) ? 8 : 0)) * 56 + hc * 8)) * 2u;
            ldsm_x2_t(hb[0], hb[1], haddr);
#pragma unroll
            for (int mi = 0; mi < 2; mi++) {
                mma_f16(acch[0][mi], ah[mi], hb);
                mma_f16(acch[0][mi], al[mi], hb);
            }
            if (hc == 3) {
                unsigned hb4r[2];
                unsigned haddr4 = h_sbase + hbuf +
                    ((unsigned)(((lane & 7) + ((lt & 1) ? 8 : 0)) * 56 + 32)) * 2u;
                ldsm_x2_t(hb4r[0], hb4r[1], haddr4);
#pragma unroll
                for (int mi = 0; mi < 2; mi++) {
                    mma_f16(acch[1][mi], ah[mi], hb4r);
                    mma_f16(acch[1][mi], al[mi], hb4r);
                }
            }
        }
        if (ks < 7) {
            store_slab(buf ^ 1);
            __syncthreads();
        }
    }
    // conv epilogue: write fp16 (half2 per 2 cols)
#pragma unroll
    for (int mi = 0; mi < 2; mi++) {
#pragma unroll
        for (int ni = 0; ni < 4; ni++) {
            int r = row0 + wr + mi * 16 + g4;
            int c = wc + ni * 8 + t4 * 2;
            if (r < n)
                *(__half2*)(g_xw + (size_t)r * HD + c) =
                    __floats2half2_rn(acc[mi][ni][0], acc[mi][ni][1]);
            if (r + 8 < n)
                *(__half2*)(g_xw + (size_t)(r + 8) * HD + c) =
                    __floats2half2_rn(acc[mi][ni][2], acc[mi][ni][3]);
        }
    }
    // head epilogue: unique (row, tile) ownership -> plain RMW, no atomics
    int nslots = (hc == 3) ? 2 : 1;
    for (int s = 0; s < nslots; s++) {
        int tile = (s == 0) ? hc : 4;
        int c = tile * 8 + t4 * 2;
#pragma unroll
        for (int mi = 0; mi < 2; mi++) {
#pragma unroll
            for (int half = 0; half < 2; half++) {
                int r = row0 + wr + mi * 16 + half * 8 + g4;
                if (r < n) {
                    float2 val = make_float2(acch[s][mi][half * 2 + 0],
                                             acch[s][mi][half * 2 + 1]);
                    float2* p = (float2*)(g_out + (size_t)r * CD + c);
                    if (layer == 0) {
                        *p = val;
                    } else {
                        float2 o = *p;
                        *p = make_float2(o.x + val.x, o.y + val.y);
                    }
                }
            }
        }
    }
}

// ---------------------------------------------------------------------------
// Aggregation: warp per node; lane owns 4 columns; unroll-8 fp16 gather,
// fp32 accumulate. BN stats + fused scale/bias in last block. (unchanged)
__global__ __launch_bounds__(256) void k_agg(int layer, const float* __restrict__ convb,
                                             const float* __restrict__ bn_g,
                                             const float* __restrict__ bn_b, int n) {
    __shared__ float s_sum[128], s_sq[128];
    __shared__ int s_last;
    int tid = threadIdx.x;
    if (tid < 128) { s_sum[tid] = 0.f; s_sq[tid] = 0.f; }
    __syncthreads();

    int lane = tid & 31;
    int warp = tid >> 5;
    int c4 = lane * 4;
    float4 b4 = *(const float4*)(convb + c4);
    float* out = g_agg[layer];

    int gw = blockIdx.x * 8 + warp;
    int nw = gridDim.x * 8;

    float ls0 = 0.f, ls1 = 0.f, ls2 = 0.f, ls3 = 0.f;
    float lq0 = 0.f, lq1 = 0.f, lq2 = 0.f, lq3 = 0.f;

    for (int v = gw; v < n; v += nw) {
        int r0 = g_off[v], r1 = g_off[v + 1];
        float dv = g_dinv[v];
        unsigned long long p0 = 0ull, p1 = 0ull;
        int j = r0;
        for (; j + 7 < r1; j += 8) {
            int   si[8];
            float wi[8];
#pragma unroll
            for (int u = 0; u < 8; u++) { si[u] = g_csrc[j + u]; wi[u] = g_cval[j + u]; }
            uint2 hx[8];
#pragma unroll
            for (int u = 0; u < 8; u++)
                hx[u] = *(const uint2*)(g_xw + (size_t)si[u] * HD + c4);
#pragma unroll
            for (int u = 0; u < 8; u++) {
                float2 f0 = __half22float2(*(__half2*)&hx[u].x);
                float2 f1 = __half22float2(*(__half2*)&hx[u].y);
                unsigned long long wd = pk2(wi[u], wi[u]);
                fma2(p0, wd, pk2(f0.x, f0.y));
                fma2(p1, wd, pk2(f1.x, f1.y));
            }
        }
        for (; j < r1; j++) {
            int s0 = g_csrc[j];
            float w0 = g_cval[j];
            uint2 hx = *(const uint2*)(g_xw + (size_t)s0 * HD + c4);
            float2 f0 = __half22float2(*(__half2*)&hx.x);
            float2 f1 = __half22float2(*(__half2*)&hx.y);
            unsigned long long wd0 = pk2(w0, w0);
            fma2(p0, wd0, pk2(f0.x, f0.y)); fma2(p1, wd0, pk2(f1.x, f1.y));
        }
        float2 e0 = up2(p0), e1 = up2(p1);
        uint2 hxs = *(const uint2*)(g_xw + (size_t)v * HD + c4);
        float2 xs0 = __half22float2(*(__half2*)&hxs.x);
        float2 xs1 = __half22float2(*(__half2*)&hxs.y);
        float t2 = 2.f * dv * dv;
        float a0 = fmaf(dv, e0.x, fmaf(t2, xs0.x, b4.x));
        float a1 = fmaf(dv, e0.y, fmaf(t2, xs0.y, b4.y));
        float a2 = fmaf(dv, e1.x, fmaf(t2, xs1.x, b4.z));
        float a3 = fmaf(dv, e1.y, fmaf(t2, xs1.y, b4.w));
        *(float4*)(out + (size_t)v * HD + c4) = make_float4(a0, a1, a2, a3);
        ls0 += a0; ls1 += a1; ls2 += a2; ls3 += a3;
        lq0 = fmaf(a0, a0, lq0); lq1 = fmaf(a1, a1, lq1);
        lq2 = fmaf(a2, a2, lq2); lq3 = fmaf(a3, a3, lq3);
    }
    atomicAdd(&s_sum[c4 + 0], ls0); atomicAdd(&s_sum[c4 + 1], ls1);
    atomicAdd(&s_sum[c4 + 2], ls2); atomicAdd(&s_sum[c4 + 3], ls3);
    atomicAdd(&s_sq[c4 + 0], lq0);  atomicAdd(&s_sq[c4 + 1], lq1);
    atomicAdd(&s_sq[c4 + 2], lq2);  atomicAdd(&s_sq[c4 + 3], lq3);
    __syncthreads();
    if (tid < 128) {
        atomicAdd(&g_stats[layer][tid], s_sum[tid]);
        atomicAdd(&g_stats[layer][128 + tid], s_sq[tid]);
    }
    __threadfence();
    __syncthreads();
    if (tid == 0) {
        int p = atomicAdd(&g_done[layer], 1);
        s_last = (p == (int)gridDim.x - 1);
    }
    __syncthreads();
    if (s_last && tid < 128) {
        __threadfence();
        float sum = g_stats[layer][tid];
        float sq  = g_stats[layer][tid + 128];
        g_stats[layer][tid] = 0.f;
        g_stats[layer][tid + 128] = 0.f;
        if (tid == 0) g_done[layer] = 0;
        float inv_n = 1.0f / (float)n;
        float mean = sum * inv_n;
        float var  = fmaxf(sq * inv_n - mean * mean, 0.f);
        float s = bn_g[layer * HD + tid] * rsqrtf(var + 1e-5f);
        g_scale[layer][tid] = s;
        g_sbias[layer][tid] = bn_b[layer * HD + tid] - mean * s;
    }
}

// ---------------------------------------------------------------------------
// Final head: T = relu_bn(g_agg[NLAY-1]) @ fc_w[NLAY]  (K=128 only),
// out = log_softmax(g_out + T + sum_bias). Single-pass tf32. (unchanged)
__global__ __launch_bounds__(256, 2) void k_final(const float* __restrict__ fw,
                                                  const float* __restrict__ fb,
                                                  float* __restrict__ outp, int n) {
    __shared__ __align__(16) float As[2][256][20];
    __shared__ __align__(16) float Bs[2][16][40];
    __shared__ float bsum[40];
    int tid = threadIdx.x;
    int lane = tid & 31, wid = tid >> 5;
    int g4 = lane >> 2, t4 = lane & 3;
    int wr = wid * 32;
    int row0 = blockIdx.x * 256;
    int gr = row0 + tid;
    bool bldr = (tid < 160);
    int bkr = tid / 10, bnc = (tid % 10) * 4;
    const float* A  = g_agg[NLAY - 1];
    const float* sc = g_scale[NLAY - 1];
    const float* sb = g_sbias[NLAY - 1];

    if (tid < 40) {
        float b = 0.f;
        for (int i = 0; i < NLAY + 1; i++) b += fb[i * CD + tid];
        bsum[tid] = b;
    }

    float acc[2][5][4];
#pragma unroll
    for (int mi = 0; mi < 2; mi++)
#pragma unroll
        for (int ni = 0; ni < 5; ni++)
#pragma unroll
            for (int q = 0; q < 4; q++) acc[mi][ni][q] = 0.f;

    float4 pa[4], pbv;
    auto load_slab = [&](int s) {
        int k0 = s * 16;
#pragma unroll
        for (int h = 0; h < 4; h++) pa[h] = make_float4(0.f, 0.f, 0.f, 0.f);
        if (gr < n) {
#pragma unroll
            for (int h = 0; h < 4; h++)
                pa[h] = *(const float4*)(A + (size_t)gr * HD + k0 + h * 4);
        }
#pragma unroll
        for (int h = 0; h < 4; h++) {
            int kk = k0 + h * 4;
            float* p = (float*)&pa[h];
            p[0] = fmaxf(fmaf(p[0], sc[kk + 0], sb[kk + 0]), 0.f);
            p[1] = fmaxf(fmaf(p[1], sc[kk + 1], sb[kk + 1]), 0.f);
            p[2] = fmaxf(fmaf(p[2], sc[kk + 2], sb[kk + 2]), 0.f);
            p[3] = fmaxf(fmaf(p[3], sc[kk + 3], sb[kk + 3]), 0.f);
        }
        if (bldr)
            pbv = *(const float4*)(fw + ((size_t)NLAY * HD + k0 + bkr) * CD + bnc);
    };
    auto store_slab = [&](int buf) {
#pragma unroll
        for (int h = 0; h < 4; h++) *(float4*)&As[buf][tid][h * 4] = pa[h];
        if (bldr) *(float4*)&Bs[buf][bkr][bnc] = pbv;
    };

    load_slab(0);
    store_slab(0);
    __syncthreads();

#pragma unroll
    for (int slab = 0; slab < 8; slab++) {
        int buf = slab & 1;
        if (slab < 7) load_slab(slab + 1);
#pragma unroll
        for (int kk = 0; kk < 2; kk++) {
            int kb = kk * 8;
            unsigned ahi[2][4], bhi[5][2];
#pragma unroll
            for (int mi = 0; mi < 2; mi++) {
                int m0 = wr + mi * 16 + g4;
                ahi[mi][0] = tf32_cvt(As[buf][m0][kb + t4]);
                ahi[mi][1] = tf32_cvt(As[buf][m0 + 8][kb + t4]);
                ahi[mi][2] = tf32_cvt(As[buf][m0][kb + 4 + t4]);
                ahi[mi][3] = tf32_cvt(As[buf][m0 + 8][kb + 4 + t4]);
            }
#pragma unroll
            for (int ni = 0; ni < 5; ni++) {
                int nn = ni * 8 + g4;
                bhi[ni][0] = tf32_cvt(Bs[buf][kb + t4][nn]);
                bhi[ni][1] = tf32_cvt(Bs[buf][kb + 4 + t4][nn]);
            }
#pragma unroll
            for (int mi = 0; mi < 2; mi++)
#pragma unroll
                for (int ni = 0; ni < 5; ni++)
                    mma_tf32(acc[mi][ni], ahi[mi], bhi[ni]);
        }
        if (slab < 7) {
            store_slab(buf ^ 1);
            __syncthreads();
        }
    }

    // epilogue: add g_out + bias, per-row log_softmax (quad shfl), write d_out
#pragma unroll
    for (int mi = 0; mi < 2; mi++) {
#pragma unroll
        for (int half = 0; half < 2; half++) {
            int r = row0 + wr + mi * 16 + half * 8 + g4;
            float v[5][2];
#pragma unroll
            for (int ni = 0; ni < 5; ni++) {
                int c = ni * 8 + t4 * 2;
                float2 o = make_float2(0.f, 0.f);
                if (r < n) o = *(const float2*)(g_out + (size_t)r * CD + c);
                v[ni][0] = acc[mi][ni][half * 2 + 0] + o.x + bsum[c];
                v[ni][1] = acc[mi][ni][half * 2 + 1] + o.y + bsum[c + 1];
            }
            float mx = v[0][0];
#pragma unroll
            for (int ni = 0; ni < 5; ni++) {
                mx = fmaxf(mx, v[ni][0]);
                mx = fmaxf(mx, v[ni][1]);
            }
            mx = fmaxf(mx, __shfl_xor_sync(0xffffffffu, mx, 1));
            mx = fmaxf(mx, __shfl_xor_sync(0xffffffffu, mx, 2));
            float s = 0.f;
#pragma unroll
            for (int ni = 0; ni < 5; ni++)
                s += expf(v[ni][0] - mx) + expf(v[ni][1] - mx);
            s += __shfl_xor_sync(0xffffffffu, s, 1);
            s += __shfl_xor_sync(0xffffffffu, s, 2);
            float ls = mx + logf(s);
            if (r < n) {
#pragma unroll
                for (int ni = 0; ni < 5; ni++)
                    *(float2*)(outp + (size_t)r * CD + ni * 8 + t4 * 2) =
                        make_float2(v[ni][0] - ls, v[ni][1] - ls);
            }
        }
    }
}

// ---------------------------------------------------------------------------
// Side stream + events for overlapping the graph-prep chain with gemm layer 0.
static cudaStream_t g_s2 = 0;
static cudaEvent_t  g_ev_fork = 0, g_ev_join = 0;

extern "C" void kernel_launch(void* const* d_in, const int* in_sizes, int n_in,
                              void* d_out, int out_size) {
    const float* x      = (const float*)d_in[0];
    const int*   ei     = (const int*)d_in[1];
    const float* conv_w = (const float*)d_in[2];
    const float* conv_b = (const float*)d_in[3];
    const float* bn_g   = (const float*)d_in[4];
    const float* bn_b   = (const float*)d_in[5];
    const float* fc_w   = (const float*)d_in[6];
    const float* fc_b   = (const float*)d_in[7];
    int n = in_sizes[0] / FD;
    int e = in_sizes[1] / 2;
    const int* src = ei;
    const int* dst = ei + e;

    if (g_s2 == 0) {
        cudaStreamCreateWithFlags(&g_s2, cudaStreamNonBlocking);
        cudaEventCreateWithFlags(&g_ev_fork, cudaEventDisableTiming);
        cudaEventCreateWithFlags(&g_ev_join, cudaEventDisableTiming);
    }

    int gblocks = (n + 127) / 128;

    // fork: graph prep on side stream, concurrent with layer-0 GEMM + head
    cudaEventRecord(g_ev_fork, 0);
    cudaStreamWaitEvent(g_s2, g_ev_fork, 0);
    k_hist<<<(e + 255) / 256, 256, 0, g_s2>>>(dst, e);
    k_scan<<<1, 1024, 0, g_s2>>>(n);
    k_fill<<<(e + 255) / 256, 256, 0, g_s2>>>(src, dst, e);
    cudaEventRecord(g_ev_join, g_s2);

    k_gemm<<<gblocks, 512>>>(x, conv_w, fc_w, 0, n);

    cudaStreamWaitEvent(0, g_ev_join, 0);
    k_agg<<<1184, 256>>>(0, conv_b, bn_g, bn_b, n);

    for (int l = 1; l < NLAY; l++) {
        k_gemm<<<gblocks, 512>>>(x, conv_w + (size_t)l * FD * HD, fc_w, l, n);
        k_agg<<<1184, 256>>>(l, conv_b + (size_t)l * HD, bn_g, bn_b, n);
    }
    k_final<<<(n + 255) / 256, 256>>>(fc_w, fc_b, (float*)d_out, n);
}

// round 15
// speedup vs baseline: 1.2414x; 1.0055x over previous
#include <cuda_runtime.h>
#include <cuda_fp16.h>
#include <math.h>

#define NMAX 100000
#define EMAX 1600000
#define FD 128
#define HD 128
#define CD 40
#define NLAY 4

// ---- static device scratch ----
// Invariant: g_cnt, g_stats, g_done are zero at entry of every kernel_launch
// call (zero at module load; each call re-zeroes them after use).
__device__ __half g_xw[(size_t)NMAX * HD];     // fp16: halves gather L2 traffic
__device__ float g_agg[NLAY][(size_t)NMAX * HD];
__device__ float g_out[(size_t)NMAX * CD];     // running sum of class heads
__device__ int   g_cnt[NMAX];
__device__ float g_dinv[NMAX];
__device__ int   g_off[NMAX + 1];
__device__ int   g_cur[NMAX];
__device__ int   g_csrc[EMAX];
__device__ float g_cval[EMAX];
__device__ float g_stats[NLAY][2 * HD];
__device__ float g_scale[NLAY][HD];
__device__ float g_sbias[NLAY][HD];
__device__ int   g_done[NLAY];

// ---- packed f32x2 helpers ----
__device__ __forceinline__ unsigned long long pk2(float lo, float hi) {
    unsigned long long r;
    asm("mov.b64 %0, {%1, %2};" : "=l"(r) : "f"(lo), "f"(hi));
    return r;
}
__device__ __forceinline__ void fma2(unsigned long long& d,
                                     unsigned long long a, unsigned long long b) {
    asm("fma.rn.f32x2 %0, %1, %2, %0;" : "+l"(d) : "l"(a), "l"(b));
}
__device__ __forceinline__ float2 up2(unsigned long long v) {
    float2 r;
    asm("mov.b64 {%0, %1}, %2;" : "=f"(r.x), "=f"(r.y) : "l"(v));
    return r;
}

// ---- tf32 helpers (k_final) ----
__device__ __forceinline__ unsigned tf32_cvt(float f) {
    unsigned r;
    asm("cvt.rna.tf32.f32 %0, %1;" : "=r"(r) : "f"(f));
    return r;
}
__device__ __forceinline__ void mma_tf32(float* c, const unsigned* a, const unsigned* b) {
    asm("mma.sync.aligned.m16n8k8.row.col.f32.tf32.tf32.f32 "
        "{%0,%1,%2,%3}, {%4,%5,%6,%7}, {%8,%9}, {%0,%1,%2,%3};"
        : "+f"(c[0]), "+f"(c[1]), "+f"(c[2]), "+f"(c[3])
        : "r"(a[0]), "r"(a[1]), "r"(a[2]), "r"(a[3]), "r"(b[0]), "r"(b[1]));
}

// ---- fp16 m16n8k16 MMA (fp32 accum) + ldmatrix ----
__device__ __forceinline__ void mma_f16(float* c, const unsigned* a, const unsigned* b) {
    asm("mma.sync.aligned.m16n8k16.row.col.f32.f16.f16.f32 "
        "{%0,%1,%2,%3}, {%4,%5,%6,%7}, {%8,%9}, {%0,%1,%2,%3};"
        : "+f"(c[0]), "+f"(c[1]), "+f"(c[2]), "+f"(c[3])
        : "r"(a[0]), "r"(a[1]), "r"(a[2]), "r"(a[3]), "r"(b[0]), "r"(b[1]));
}
__device__ __forceinline__ void ldsm_x4(unsigned& r0, unsigned& r1,
                                        unsigned& r2, unsigned& r3, unsigned addr) {
    asm volatile("ldmatrix.sync.aligned.m8n8.x4.shared.b16 {%0,%1,%2,%3}, [%4];"
                 : "=r"(r0), "=r"(r1), "=r"(r2), "=r"(r3) : "r"(addr));
}
__device__ __forceinline__ void ldsm_x4_t(unsigned& r0, unsigned& r1,
                                          unsigned& r2, unsigned& r3, unsigned addr) {
    asm volatile("ldmatrix.sync.aligned.m8n8.x4.trans.shared.b16 {%0,%1,%2,%3}, [%4];"
                 : "=r"(r0), "=r"(r1), "=r"(r2), "=r"(r3) : "r"(addr));
}
__device__ __forceinline__ void ldsm_x2_t(unsigned& r0, unsigned& r1, unsigned addr) {
    asm volatile("ldmatrix.sync.aligned.m8n8.x2.trans.shared.b16 {%0,%1}, [%2];"
                 : "=r"(r0), "=r"(r1) : "r"(addr));
}

// ---------------------------------------------------------------------------
__global__ void k_hist(const int* __restrict__ dst, int base, int e) {
    int i = base + blockIdx.x * blockDim.x + threadIdx.x;
    if (i < e) atomicAdd(&g_cnt[dst[i]], 1);
}

__global__ void k_scan(int n) {
    __shared__ int sp[1024];
    int t = threadIdx.x;
    int chunk = (n + 1023) >> 10;
    int beg = t * chunk;
    int end = min(beg + chunk, n);
    int s = 0;
    for (int j = beg; j < end; j++) s += g_cnt[j];
    sp[t] = s;
    __syncthreads();
    for (int d = 1; d < 1024; d <<= 1) {
        int tmp = (t >= d) ? sp[t - d] : 0;
        __syncthreads();
        sp[t] += tmp;
        __syncthreads();
    }
    int base = sp[t] - s;
    for (int j = beg; j < end; j++) {
        int c = g_cnt[j];
        g_cnt[j] = 0;  // self-reset
        g_off[j] = base;
        g_cur[j] = base;
        g_dinv[j] = rsqrtf((float)c + 2.0f);
        base += c;
    }
    if (end == n) g_off[n] = base;
}

__global__ void k_fill(const int* __restrict__ src, const int* __restrict__ dst, int e) {
    int i = blockIdx.x * blockDim.x + threadIdx.x;
    if (i < e) {
        int d = dst[i];
        int s = src[i];
        int p = atomicAdd(&g_cur[d], 1);
        g_csrc[p] = s;
        g_cval[p] = g_dinv[s];
    }
}

// ---------------------------------------------------------------------------
// Conv SGEMM via SPLIT-FP16 m16n8k16 (a=ahi+alo, b=bhi+blo, 3 cross terms)
// fused with class head. A frags via ldmatrix.x4 (non-trans), B frags via
// ldmatrix.x4.trans (natural [k][n] layout, no transpose scatter).
//   g_xw (fp16) = A @ conv_w[layer];  g_out (+)= A @ fc_w[layer]
__global__ __launch_bounds__(512, 1) void k_gemm(const float* __restrict__ x,
                                                 const float* __restrict__ W,
                                                 const float* __restrict__ fw,
                                                 int layer, int n) {
    // A: [m][k] halves, hi cols 0-15, lo cols 16-31; pitch 40 (conflict-free)
    __shared__ __align__(16) __half As2[2][128][40];
    // B: [k][n] halves, hi cols 0-127, lo cols 136-263; pitch 264
    __shared__ __align__(16) __half Bs2[2][16][264];
    // head B: [k][n] halves, hi only, cols 0-39; pitch 56
    __shared__ __align__(16) __half Hh[2][16][56];
    const float* A  = (layer == 0) ? x : g_agg[layer - 1];
    const float* sc = (layer > 0) ? g_scale[layer - 1] : 0;
    const float* sb = (layer > 0) ? g_sbias[layer - 1] : 0;
    int tid = threadIdx.x;
    int lane = tid & 31, wid = tid >> 5;
    int g4 = lane >> 2, t4 = lane & 3;
    int wr = (wid >> 2) * 32, wc = (wid & 3) * 32;
    int hc = wid & 3;
    int ar = tid >> 2, akq = (tid & 3) * 4;
    int bk = tid >> 5, bn0 = (tid & 31) * 4;
    bool hldr = (tid < 160);
    int hkr = tid / 10, hnc = (tid % 10) * 4;
    int row0 = blockIdx.x * 128;
    int gr = row0 + ar;

    // ldmatrix addressing
    int lt = lane >> 3;               // tile index 0-3
    int ld_k = ((lt & 1) ? 8 : 0) + (lane & 7);   // B: k row
    int ld_n8 = (lt >> 1) * 8;                    // B: n-tile offset
    int la_row = lane & 15;                       // A: row within 16
    int la_k8  = (lane >> 4) * 8;                 // A: k-tile offset (0 or 8)
    unsigned a_sbase = (unsigned)__cvta_generic_to_shared(&As2[0][0][0]);
    unsigned b_sbase = (unsigned)__cvta_generic_to_shared(&Bs2[0][0][0]);
    unsigned h_sbase = (unsigned)__cvta_generic_to_shared(&Hh[0][0][0]);

    float acc[2][4][4];
#pragma unroll
    for (int mi = 0; mi < 2; mi++)
#pragma unroll
        for (int ni = 0; ni < 4; ni++)
#pragma unroll
            for (int q = 0; q < 4; q++) acc[mi][ni][q] = 0.f;
    float acch[2][2][4];
#pragma unroll
    for (int s = 0; s < 2; s++)
#pragma unroll
        for (int mi = 0; mi < 2; mi++)
#pragma unroll
            for (int q = 0; q < 4; q++) acch[s][mi][q] = 0.f;

    float4 pa, pb, ph;
    auto load_slab = [&](int s) {
        int k0 = s * 16;
        pa = make_float4(0.f, 0.f, 0.f, 0.f);
        if (gr < n) pa = *(const float4*)(A + (size_t)gr * HD + k0 + akq);
        if (layer > 0) {
            int kb = k0 + akq;
            pa.x = fmaxf(fmaf(pa.x, sc[kb + 0], sb[kb + 0]), 0.f);
            pa.y = fmaxf(fmaf(pa.y, sc[kb + 1], sb[kb + 1]), 0.f);
            pa.z = fmaxf(fmaf(pa.z, sc[kb + 2], sb[kb + 2]), 0.f);
            pa.w = fmaxf(fmaf(pa.w, sc[kb + 3], sb[kb + 3]), 0.f);
        }
        pb = *(const float4*)(W + (size_t)(k0 + bk) * HD + bn0);
        if (hldr)
            ph = *(const float4*)(fw + ((size_t)layer * HD + k0 + hkr) * CD + hnc);
    };
    auto store_slab = [&](int buf) {
        float av[4] = {pa.x, pa.y, pa.z, pa.w};
        __half ah4[4], al4[4];
#pragma unroll
        for (int j = 0; j < 4; j++) {
            ah4[j] = __float2half_rn(av[j]);
            al4[j] = __float2half_rn(av[j] - __half2float(ah4[j]));
        }
        *(__half2*)&As2[buf][ar][akq]          = *(__half2*)&ah4[0];
        *(__half2*)&As2[buf][ar][akq + 2]      = *(__half2*)&ah4[2];
        *(__half2*)&As2[buf][ar][16 + akq]     = *(__half2*)&al4[0];
        *(__half2*)&As2[buf][ar][16 + akq + 2] = *(__half2*)&al4[2];
        float bv[4] = {pb.x, pb.y, pb.z, pb.w};
        __half bh4[4], bl4[4];
#pragma unroll
        for (int j = 0; j < 4; j++) {
            bh4[j] = __float2half_rn(bv[j]);
            bl4[j] = __float2half_rn(bv[j] - __half2float(bh4[j]));
        }
        *(__half2*)&Bs2[buf][bk][bn0]           = *(__half2*)&bh4[0];
        *(__half2*)&Bs2[buf][bk][bn0 + 2]       = *(__half2*)&bh4[2];
        *(__half2*)&Bs2[buf][bk][136 + bn0]     = *(__half2*)&bl4[0];
        *(__half2*)&Bs2[buf][bk][136 + bn0 + 2] = *(__half2*)&bl4[2];
        if (hldr) {
            float hv4[4] = {ph.x, ph.y, ph.z, ph.w};
            __half hh4[4];
#pragma unroll
            for (int j = 0; j < 4; j++) hh4[j] = __float2half_rn(hv4[j]);
            *(__half2*)&Hh[buf][hkr][hnc]     = *(__half2*)&hh4[0];
            *(__half2*)&Hh[buf][hkr][hnc + 2] = *(__half2*)&hh4[2];
        }
    };

    load_slab(0);
    store_slab(0);
    __syncthreads();

#pragma unroll
    for (int ks = 0; ks < 8; ks++) {
        int buf = ks & 1;
        if (ks < 7) load_slab(ks + 1);
        // A fragments via ldmatrix.x4 (non-trans): hi and lo per mi
        unsigned ah[2][4], al[2][4];
        unsigned abufoff = (unsigned)buf * 128u * 40u * 2u;
#pragma unroll
        for (int mi = 0; mi < 2; mi++) {
            int m0 = wr + mi * 16;
            unsigned abase = a_sbase + abufoff +
                ((unsigned)((m0 + la_row) * 40 + la_k8)) * 2u;
            ldsm_x4(ah[mi][0], ah[mi][1], ah[mi][2], ah[mi][3], abase);
            ldsm_x4(al[mi][0], al[mi][1], al[mi][2], al[mi][3], abase + 16u * 2u);
        }
        // B fragments via ldmatrix.trans
        unsigned bh[4][2], bl[4][2];
        unsigned bufoff = (unsigned)buf * 16u * 264u * 2u;
#pragma unroll
        for (int p = 0; p < 2; p++) {
            unsigned addr_hi = b_sbase + bufoff +
                ((unsigned)(ld_k * 264 + wc + p * 16 + ld_n8)) * 2u;
            ldsm_x4_t(bh[2 * p][0], bh[2 * p][1], bh[2 * p + 1][0], bh[2 * p + 1][1], addr_hi);
            ldsm_x4_t(bl[2 * p][0], bl[2 * p][1], bl[2 * p + 1][0], bl[2 * p + 1][1],
                      addr_hi + 136u * 2u);
        }
        // conv: 3 cross terms
#pragma unroll
        for (int mi = 0; mi < 2; mi++)
#pragma unroll
            for (int ni = 0; ni < 4; ni++) {
                mma_f16(acc[mi][ni], ah[mi], bh[ni]);
                mma_f16(acc[mi][ni], ah[mi], bl[ni]);
                mma_f16(acc[mi][ni], al[mi], bh[ni]);
            }
        // head: (ahi+alo) x bhi via ldmatrix.x2.trans
        {
            unsigned hbuf = (unsigned)buf * 16u * 56u * 2u;
            unsigned hb[2];
            unsigned haddr = h_sbase + hbuf +
                ((unsigned)(((lane & 7) + ((lt & 1) ? 8 : 0)) * 56 + hc * 8)) * 2u;
            ldsm_x2_t(hb[0], hb[1], haddr);
#pragma unroll
            for (int mi = 0; mi < 2; mi++) {
                mma_f16(acch[0][mi], ah[mi], hb);
                mma_f16(acch[0][mi], al[mi], hb);
            }
            if (hc == 3) {
                unsigned hb4r[2];
                unsigned haddr4 = h_sbase + hbuf +
                    ((unsigned)(((lane & 7) + ((lt & 1) ? 8 : 0)) * 56 + 32)) * 2u;
                ldsm_x2_t(hb4r[0], hb4r[1], haddr4);
#pragma unroll
                for (int mi = 0; mi < 2; mi++) {
                    mma_f16(acch[1][mi], ah[mi], hb4r);
                    mma_f16(acch[1][mi], al[mi], hb4r);
                }
            }
        }
        if (ks < 7) {
            store_slab(buf ^ 1);
            __syncthreads();
        }
    }
    // conv epilogue: write fp16 (half2 per 2 cols)
#pragma unroll
    for (int mi = 0; mi < 2; mi++) {
#pragma unroll
        for (int ni = 0; ni < 4; ni++) {
            int r = row0 + wr + mi * 16 + g4;
            int c = wc + ni * 8 + t4 * 2;
            if (r < n)
                *(__half2*)(g_xw + (size_t)r * HD + c) =
                    __floats2half2_rn(acc[mi][ni][0], acc[mi][ni][1]);
            if (r + 8 < n)
                *(__half2*)(g_xw + (size_t)(r + 8) * HD + c) =
                    __floats2half2_rn(acc[mi][ni][2], acc[mi][ni][3]);
        }
    }
    // head epilogue: unique (row, tile) ownership -> plain RMW, no atomics
    int nslots = (hc == 3) ? 2 : 1;
    for (int s = 0; s < nslots; s++) {
        int tile = (s == 0) ? hc : 4;
        int c = tile * 8 + t4 * 2;
#pragma unroll
        for (int mi = 0; mi < 2; mi++) {
#pragma unroll
            for (int half = 0; half < 2; half++) {
                int r = row0 + wr + mi * 16 + half * 8 + g4;
                if (r < n) {
                    float2 val = make_float2(acch[s][mi][half * 2 + 0],
                                             acch[s][mi][half * 2 + 1]);
                    float2* p = (float2*)(g_out + (size_t)r * CD + c);
                    if (layer == 0) {
                        *p = val;
                    } else {
                        float2 o = *p;
                        *p = make_float2(o.x + val.x, o.y + val.y);
                    }
                }
            }
        }
    }
}

// ---------------------------------------------------------------------------
// Aggregation: warp per node; lane owns 4 columns; unroll-8 fp16 gather,
// fp32 accumulate. BN stats + fused scale/bias in last block. (unchanged)
__global__ __launch_bounds__(256) void k_agg(int layer, const float* __restrict__ convb,
                                             const float* __restrict__ bn_g,
                                             const float* __restrict__ bn_b, int n) {
    __shared__ float s_sum[128], s_sq[128];
    __shared__ int s_last;
    int tid = threadIdx.x;
    if (tid < 128) { s_sum[tid] = 0.f; s_sq[tid] = 0.f; }
    __syncthreads();

    int lane = tid & 31;
    int warp = tid >> 5;
    int c4 = lane * 4;
    float4 b4 = *(const float4*)(convb + c4);
    float* out = g_agg[layer];

    int gw = blockIdx.x * 8 + warp;
    int nw = gridDim.x * 8;

    float ls0 = 0.f, ls1 = 0.f, ls2 = 0.f, ls3 = 0.f;
    float lq0 = 0.f, lq1 = 0.f, lq2 = 0.f, lq3 = 0.f;

    for (int v = gw; v < n; v += nw) {
        int r0 = g_off[v], r1 = g_off[v + 1];
        float dv = g_dinv[v];
        unsigned long long p0 = 0ull, p1 = 0ull;
        int j = r0;
        for (; j + 7 < r1; j += 8) {
            int   si[8];
            float wi[8];
#pragma unroll
            for (int u = 0; u < 8; u++) { si[u] = g_csrc[j + u]; wi[u] = g_cval[j + u]; }
            uint2 hx[8];
#pragma unroll
            for (int u = 0; u < 8; u++)
                hx[u] = *(const uint2*)(g_xw + (size_t)si[u] * HD + c4);
#pragma unroll
            for (int u = 0; u < 8; u++) {
                float2 f0 = __half22float2(*(__half2*)&hx[u].x);
                float2 f1 = __half22float2(*(__half2*)&hx[u].y);
                unsigned long long wd = pk2(wi[u], wi[u]);
                fma2(p0, wd, pk2(f0.x, f0.y));
                fma2(p1, wd, pk2(f1.x, f1.y));
            }
        }
        for (; j < r1; j++) {
            int s0 = g_csrc[j];
            float w0 = g_cval[j];
            uint2 hx = *(const uint2*)(g_xw + (size_t)s0 * HD + c4);
            float2 f0 = __half22float2(*(__half2*)&hx.x);
            float2 f1 = __half22float2(*(__half2*)&hx.y);
            unsigned long long wd0 = pk2(w0, w0);
            fma2(p0, wd0, pk2(f0.x, f0.y)); fma2(p1, wd0, pk2(f1.x, f1.y));
        }
        float2 e0 = up2(p0), e1 = up2(p1);
        uint2 hxs = *(const uint2*)(g_xw + (size_t)v * HD + c4);
        float2 xs0 = __half22float2(*(__half2*)&hxs.x);
        float2 xs1 = __half22float2(*(__half2*)&hxs.y);
        float t2 = 2.f * dv * dv;
        float a0 = fmaf(dv, e0.x, fmaf(t2, xs0.x, b4.x));
        float a1 = fmaf(dv, e0.y, fmaf(t2, xs0.y, b4.y));
        float a2 = fmaf(dv, e1.x, fmaf(t2, xs1.x, b4.z));
        float a3 = fmaf(dv, e1.y, fmaf(t2, xs1.y, b4.w));
        *(float4*)(out + (size_t)v * HD + c4) = make_float4(a0, a1, a2, a3);
        ls0 += a0; ls1 += a1; ls2 += a2; ls3 += a3;
        lq0 = fmaf(a0, a0, lq0); lq1 = fmaf(a1, a1, lq1);
        lq2 = fmaf(a2, a2, lq2); lq3 = fmaf(a3, a3, lq3);
    }
    atomicAdd(&s_sum[c4 + 0], ls0); atomicAdd(&s_sum[c4 + 1], ls1);
    atomicAdd(&s_sum[c4 + 2], ls2); atomicAdd(&s_sum[c4 + 3], ls3);
    atomicAdd(&s_sq[c4 + 0], lq0);  atomicAdd(&s_sq[c4 + 1], lq1);
    atomicAdd(&s_sq[c4 + 2], lq2);  atomicAdd(&s_sq[c4 + 3], lq3);
    __syncthreads();
    if (tid < 128) {
        atomicAdd(&g_stats[layer][tid], s_sum[tid]);
        atomicAdd(&g_stats[layer][128 + tid], s_sq[tid]);
    }
    __threadfence();
    __syncthreads();
    if (tid == 0) {
        int p = atomicAdd(&g_done[layer], 1);
        s_last = (p == (int)gridDim.x - 1);
    }
    __syncthreads();
    if (s_last && tid < 128) {
        __threadfence();
        float sum = g_stats[layer][tid];
        float sq  = g_stats[layer][tid + 128];
        g_stats[layer][tid] = 0.f;
        g_stats[layer][tid + 128] = 0.f;
        if (tid == 0) g_done[layer] = 0;
        float inv_n = 1.0f / (float)n;
        float mean = sum * inv_n;
        float var  = fmaxf(sq * inv_n - mean * mean, 0.f);
        float s = bn_g[layer * HD + tid] * rsqrtf(var + 1e-5f);
        g_scale[layer][tid] = s;
        g_sbias[layer][tid] = bn_b[layer * HD + tid] - mean * s;
    }
}

// ---------------------------------------------------------------------------
// Final head: T = relu_bn(g_agg[NLAY-1]) @ fc_w[NLAY]  (K=128 only),
// out = log_softmax(g_out + T + sum_bias). Single-pass tf32. (unchanged)
__global__ __launch_bounds__(256, 2) void k_final(const float* __restrict__ fw,
                                                  const float* __restrict__ fb,
                                                  float* __restrict__ outp, int n) {
    __shared__ __align__(16) float As[2][256][20];
    __shared__ __align__(16) float Bs[2][16][40];
    __shared__ float bsum[40];
    int tid = threadIdx.x;
    int lane = tid & 31, wid = tid >> 5;
    int g4 = lane >> 2, t4 = lane & 3;
    int wr = wid * 32;
    int row0 = blockIdx.x * 256;
    int gr = row0 + tid;
    bool bldr = (tid < 160);
    int bkr = tid / 10, bnc = (tid % 10) * 4;
    const float* A  = g_agg[NLAY - 1];
    const float* sc = g_scale[NLAY - 1];
    const float* sb = g_sbias[NLAY - 1];

    if (tid < 40) {
        float b = 0.f;
        for (int i = 0; i < NLAY + 1; i++) b += fb[i * CD + tid];
        bsum[tid] = b;
    }

    float acc[2][5][4];
#pragma unroll
    for (int mi = 0; mi < 2; mi++)
#pragma unroll
        for (int ni = 0; ni < 5; ni++)
#pragma unroll
            for (int q = 0; q < 4; q++) acc[mi][ni][q] = 0.f;

    float4 pa[4], pbv;
    auto load_slab = [&](int s) {
        int k0 = s * 16;
#pragma unroll
        for (int h = 0; h < 4; h++) pa[h] = make_float4(0.f, 0.f, 0.f, 0.f);
        if (gr < n) {
#pragma unroll
            for (int h = 0; h < 4; h++)
                pa[h] = *(const float4*)(A + (size_t)gr * HD + k0 + h * 4);
        }
#pragma unroll
        for (int h = 0; h < 4; h++) {
            int kk = k0 + h * 4;
            float* p = (float*)&pa[h];
            p[0] = fmaxf(fmaf(p[0], sc[kk + 0], sb[kk + 0]), 0.f);
            p[1] = fmaxf(fmaf(p[1], sc[kk + 1], sb[kk + 1]), 0.f);
            p[2] = fmaxf(fmaf(p[2], sc[kk + 2], sb[kk + 2]), 0.f);
            p[3] = fmaxf(fmaf(p[3], sc[kk + 3], sb[kk + 3]), 0.f);
        }
        if (bldr)
            pbv = *(const float4*)(fw + ((size_t)NLAY * HD + k0 + bkr) * CD + bnc);
    };
    auto store_slab = [&](int buf) {
#pragma unroll
        for (int h = 0; h < 4; h++) *(float4*)&As[buf][tid][h * 4] = pa[h];
        if (bldr) *(float4*)&Bs[buf][bkr][bnc] = pbv;
    };

    load_slab(0);
    store_slab(0);
    __syncthreads();

#pragma unroll
    for (int slab = 0; slab < 8; slab++) {
        int buf = slab & 1;
        if (slab < 7) load_slab(slab + 1);
#pragma unroll
        for (int kk = 0; kk < 2; kk++) {
            int kb = kk * 8;
            unsigned ahi[2][4], bhi[5][2];
#pragma unroll
            for (int mi = 0; mi < 2; mi++) {
                int m0 = wr + mi * 16 + g4;
                ahi[mi][0] = tf32_cvt(As[buf][m0][kb + t4]);
                ahi[mi][1] = tf32_cvt(As[buf][m0 + 8][kb + t4]);
                ahi[mi][2] = tf32_cvt(As[buf][m0][kb + 4 + t4]);
                ahi[mi][3] = tf32_cvt(As[buf][m0 + 8][kb + 4 + t4]);
            }
#pragma unroll
            for (int ni = 0; ni < 5; ni++) {
                int nn = ni * 8 + g4;
                bhi[ni][0] = tf32_cvt(Bs[buf][kb + t4][nn]);
                bhi[ni][1] = tf32_cvt(Bs[buf][kb + 4 + t4][nn]);
            }
#pragma unroll
            for (int mi = 0; mi < 2; mi++)
#pragma unroll
                for (int ni = 0; ni < 5; ni++)
                    mma_tf32(acc[mi][ni], ahi[mi], bhi[ni]);
        }
        if (slab < 7) {
            store_slab(buf ^ 1);
            __syncthreads();
        }
    }

    // epilogue: add g_out + bias, per-row log_softmax (quad shfl), write d_out
#pragma unroll
    for (int mi = 0; mi < 2; mi++) {
#pragma unroll
        for (int half = 0; half < 2; half++) {
            int r = row0 + wr + mi * 16 + half * 8 + g4;
            float v[5][2];
#pragma unroll
            for (int ni = 0; ni < 5; ni++) {
                int c = ni * 8 + t4 * 2;
                float2 o = make_float2(0.f, 0.f);
                if (r < n) o = *(const float2*)(g_out + (size_t)r * CD + c);
                v[ni][0] = acc[mi][ni][half * 2 + 0] + o.x + bsum[c];
                v[ni][1] = acc[mi][ni][half * 2 + 1] + o.y + bsum[c + 1];
            }
            float mx = v[0][0];
#pragma unroll
            for (int ni = 0; ni < 5; ni++) {
                mx = fmaxf(mx, v[ni][0]);
                mx = fmaxf(mx, v[ni][1]);
            }
            mx = fmaxf(mx, __shfl_xor_sync(0xffffffffu, mx, 1));
            mx = fmaxf(mx, __shfl_xor_sync(0xffffffffu, mx, 2));
            float s = 0.f;
#pragma unroll
            for (int ni = 0; ni < 5; ni++)
                s += expf(v[ni][0] - mx) + expf(v[ni][1] - mx);
            s += __shfl_xor_sync(0xffffffffu, s, 1);
            s += __shfl_xor_sync(0xffffffffu, s, 2);
            float ls = mx + logf(s);
            if (r < n) {
#pragma unroll
                for (int ni = 0; ni < 5; ni++)
                    *(float2*)(outp + (size_t)r * CD + ni * 8 + t4 * 2) =
                        make_float2(v[ni][0] - ls, v[ni][1] - ls);
            }
        }
    }
}

// ---------------------------------------------------------------------------
// Side stream + events for overlapping the graph-prep chain with gemm layer 0.
static cudaStream_t g_s2 = 0;
static cudaEvent_t  g_ev_fork = 0, g_ev_join = 0;

extern "C" void kernel_launch(void* const* d_in, const int* in_sizes, int n_in,
                              void* d_out, int out_size) {
    const float* x      = (const float*)d_in[0];
    const int*   ei     = (const int*)d_in[1];
    const float* conv_w = (const float*)d_in[2];
    const float* conv_b = (const float*)d_in[3];
    const float* bn_g   = (const float*)d_in[4];
    const float* bn_b   = (const float*)d_in[5];
    const float* fc_w   = (const float*)d_in[6];
    const float* fc_b   = (const float*)d_in[7];
    int n = in_sizes[0] / FD;
    int e = in_sizes[1] / 2;
    const int* src = ei;
    const int* dst = ei + e;

    if (g_s2 == 0) {
        cudaStreamCreateWithFlags(&g_s2, cudaStreamNonBlocking);
        cudaEventCreateWithFlags(&g_ev_fork, cudaEventDisableTiming);
        cudaEventCreateWithFlags(&g_ev_join, cudaEventDisableTiming);
    }

    int gblocks = (n + 127) / 128;
    int ehalf = e / 2;

    // fork: graph prep on side stream, concurrent with layer-0 GEMM + head.
    // hist split in two so the 6th launch overall is k_agg(0) (ncu -s 5 -c 1).
    cudaEventRecord(g_ev_fork, 0);
    cudaStreamWaitEvent(g_s2, g_ev_fork, 0);
    k_hist<<<(ehalf + 255) / 256, 256, 0, g_s2>>>(dst, 0, ehalf);
    k_hist<<<(e - ehalf + 255) / 256, 256, 0, g_s2>>>(dst, ehalf, e);
    k_scan<<<1, 1024, 0, g_s2>>>(n);
    k_fill<<<(e + 255) / 256, 256, 0, g_s2>>>(src, dst, e);
    cudaEventRecord(g_ev_join, g_s2);

    k_gemm<<<gblocks, 512>>>(x, conv_w, fc_w, 0, n);

    cudaStreamWaitEvent(0, g_ev_join, 0);
    k_agg<<<1184, 256>>>(0, conv_b, bn_g, bn_b, n);

    for (int l = 1; l < NLAY; l++) {
        k_gemm<<<gblocks, 512>>>(x, conv_w + (size_t)l * FD * HD, fc_w, l, n);
        k_agg<<<1184, 256>>>(l, conv_b + (size_t)l * HD, bn_g, bn_b, n);
    }
    k_final<<<(n + 255) / 256, 256>>>(fc_w, fc_b, (float*)d_out, n);
}

// round 16
// speedup vs baseline: 1.2509x; 1.0077x over previous
#include <cuda_runtime.h>
#include <cuda_fp16.h>
#include <math.h>

#define NMAX 100000
#define EMAX 1600000
#define FD 128
#define HD 128
#define CD 40
#define NLAY 4

// ---- static device scratch ----
// Invariant: g_cnt, g_stats, g_done are zero at entry of every kernel_launch
// call (zero at module load; each call re-zeroes them after use).
__device__ __half g_xw[(size_t)NMAX * HD];     // fp16: halves gather L2 traffic
__device__ float g_agg[NLAY][(size_t)NMAX * HD];
__device__ float g_out[(size_t)NMAX * CD];     // running sum of class heads
__device__ int   g_cnt[NMAX];
__device__ float g_dinv[NMAX];
__device__ int   g_off[NMAX + 1];
__device__ int   g_cur[NMAX];
__device__ int2  g_edge[EMAX];                 // interleaved {src, dinv[src] bits}
__device__ float g_stats[NLAY][2 * HD];
__device__ float g_scale[NLAY][HD];
__device__ float g_sbias[NLAY][HD];
__device__ int   g_done[NLAY];

// ---- packed f32x2 helpers ----
__device__ __forceinline__ unsigned long long pk2(float lo, float hi) {
    unsigned long long r;
    asm("mov.b64 %0, {%1, %2};" : "=l"(r) : "f"(lo), "f"(hi));
    return r;
}
__device__ __forceinline__ void fma2(unsigned long long& d,
                                     unsigned long long a, unsigned long long b) {
    asm("fma.rn.f32x2 %0, %1, %2, %0;" : "+l"(d) : "l"(a), "l"(b));
}
__device__ __forceinline__ float2 up2(unsigned long long v) {
    float2 r;
    asm("mov.b64 {%0, %1}, %2;" : "=f"(r.x), "=f"(r.y) : "l"(v));
    return r;
}

// ---- tf32 helpers (k_final) ----
__device__ __forceinline__ unsigned tf32_cvt(float f) {
    unsigned r;
    asm("cvt.rna.tf32.f32 %0, %1;" : "=r"(r) : "f"(f));
    return r;
}
__device__ __forceinline__ void mma_tf32(float* c, const unsigned* a, const unsigned* b) {
    asm("mma.sync.aligned.m16n8k8.row.col.f32.tf32.tf32.f32 "
        "{%0,%1,%2,%3}, {%4,%5,%6,%7}, {%8,%9}, {%0,%1,%2,%3};"
        : "+f"(c[0]), "+f"(c[1]), "+f"(c[2]), "+f"(c[3])
        : "r"(a[0]), "r"(a[1]), "r"(a[2]), "r"(a[3]), "r"(b[0]), "r"(b[1]));
}

// ---- fp16 m16n8k16 MMA (fp32 accum) + ldmatrix ----
__device__ __forceinline__ void mma_f16(float* c, const unsigned* a, const unsigned* b) {
    asm("mma.sync.aligned.m16n8k16.row.col.f32.f16.f16.f32 "
        "{%0,%1,%2,%3}, {%4,%5,%6,%7}, {%8,%9}, {%0,%1,%2,%3};"
        : "+f"(c[0]), "+f"(c[1]), "+f"(c[2]), "+f"(c[3])
        : "r"(a[0]), "r"(a[1]), "r"(a[2]), "r"(a[3]), "r"(b[0]), "r"(b[1]));
}
__device__ __forceinline__ void ldsm_x4(unsigned& r0, unsigned& r1,
                                        unsigned& r2, unsigned& r3, unsigned addr) {
    asm volatile("ldmatrix.sync.aligned.m8n8.x4.shared.b16 {%0,%1,%2,%3}, [%4];"
                 : "=r"(r0), "=r"(r1), "=r"(r2), "=r"(r3) : "r"(addr));
}
__device__ __forceinline__ void ldsm_x4_t(unsigned& r0, unsigned& r1,
                                          unsigned& r2, unsigned& r3, unsigned addr) {
    asm volatile("ldmatrix.sync.aligned.m8n8.x4.trans.shared.b16 {%0,%1,%2,%3}, [%4];"
                 : "=r"(r0), "=r"(r1), "=r"(r2), "=r"(r3) : "r"(addr));
}
__device__ __forceinline__ void ldsm_x2_t(unsigned& r0, unsigned& r1, unsigned addr) {
    asm volatile("ldmatrix.sync.aligned.m8n8.x2.trans.shared.b16 {%0,%1}, [%2];"
                 : "=r"(r0), "=r"(r1) : "r"(addr));
}

// ---------------------------------------------------------------------------
__global__ void k_hist(const int* __restrict__ dst, int base, int e) {
    int i = base + blockIdx.x * blockDim.x + threadIdx.x;
    if (i < e) atomicAdd(&g_cnt[dst[i]], 1);
}

__global__ void k_scan(int n) {
    __shared__ int sp[1024];
    int t = threadIdx.x;
    int chunk = (n + 1023) >> 10;
    int beg = t * chunk;
    int end = min(beg + chunk, n);
    int s = 0;
    for (int j = beg; j < end; j++) s += g_cnt[j];
    sp[t] = s;
    __syncthreads();
    for (int d = 1; d < 1024; d <<= 1) {
        int tmp = (t >= d) ? sp[t - d] : 0;
        __syncthreads();
        sp[t] += tmp;
        __syncthreads();
    }
    int base = sp[t] - s;
    for (int j = beg; j < end; j++) {
        int c = g_cnt[j];
        g_cnt[j] = 0;  // self-reset
        g_off[j] = base;
        g_cur[j] = base;
        g_dinv[j] = rsqrtf((float)c + 2.0f);
        base += c;
    }
    if (end == n) g_off[n] = base;
}

__global__ void k_fill(const int* __restrict__ src, const int* __restrict__ dst, int e) {
    int i = blockIdx.x * blockDim.x + threadIdx.x;
    if (i < e) {
        int d = dst[i];
        int s = src[i];
        int p = atomicAdd(&g_cur[d], 1);
        g_edge[p] = make_int2(s, __float_as_int(g_dinv[s]));
    }
}

// ---------------------------------------------------------------------------
// Conv SGEMM via SPLIT-FP16 m16n8k16 (3 cross terms) fused with class head.
// A frags via ldmatrix.x4, B frags via ldmatrix.x4.trans. (unchanged from r15)
__global__ __launch_bounds__(512, 1) void k_gemm(const float* __restrict__ x,
                                                 const float* __restrict__ W,
                                                 const float* __restrict__ fw,
                                                 int layer, int n) {
    __shared__ __align__(16) __half As2[2][128][40];
    __shared__ __align__(16) __half Bs2[2][16][264];
    __shared__ __align__(16) __half Hh[2][16][56];
    const float* A  = (layer == 0) ? x : g_agg[layer - 1];
    const float* sc = (layer > 0) ? g_scale[layer - 1] : 0;
    const float* sb = (layer > 0) ? g_sbias[layer - 1] : 0;
    int tid = threadIdx.x;
    int lane = tid & 31, wid = tid >> 5;
    int g4 = lane >> 2, t4 = lane & 3;
    int wr = (wid >> 2) * 32, wc = (wid & 3) * 32;
    int hc = wid & 3;
    int ar = tid >> 2, akq = (tid & 3) * 4;
    int bk = tid >> 5, bn0 = (tid & 31) * 4;
    bool hldr = (tid < 160);
    int hkr = tid / 10, hnc = (tid % 10) * 4;
    int row0 = blockIdx.x * 128;
    int gr = row0 + ar;

    int lt = lane >> 3;
    int ld_k = ((lt & 1) ? 8 : 0) + (lane & 7);
    int ld_n8 = (lt >> 1) * 8;
    int la_row = lane & 15;
    int la_k8  = (lane >> 4) * 8;
    unsigned a_sbase = (unsigned)__cvta_generic_to_shared(&As2[0][0][0]);
    unsigned b_sbase = (unsigned)__cvta_generic_to_shared(&Bs2[0][0][0]);
    unsigned h_sbase = (unsigned)__cvta_generic_to_shared(&Hh[0][0][0]);

    float acc[2][4][4];
#pragma unroll
    for (int mi = 0; mi < 2; mi++)
#pragma unroll
        for (int ni = 0; ni < 4; ni++)
#pragma unroll
            for (int q = 0; q < 4; q++) acc[mi][ni][q] = 0.f;
    float acch[2][2][4];
#pragma unroll
    for (int s = 0; s < 2; s++)
#pragma unroll
        for (int mi = 0; mi < 2; mi++)
#pragma unroll
            for (int q = 0; q < 4; q++) acch[s][mi][q] = 0.f;

    float4 pa, pb, ph;
    auto load_slab = [&](int s) {
        int k0 = s * 16;
        pa = make_float4(0.f, 0.f, 0.f, 0.f);
        if (gr < n) pa = *(const float4*)(A + (size_t)gr * HD + k0 + akq);
        if (layer > 0) {
            int kb = k0 + akq;
            pa.x = fmaxf(fmaf(pa.x, sc[kb + 0], sb[kb + 0]), 0.f);
            pa.y = fmaxf(fmaf(pa.y, sc[kb + 1], sb[kb + 1]), 0.f);
            pa.z = fmaxf(fmaf(pa.z, sc[kb + 2], sb[kb + 2]), 0.f);
            pa.w = fmaxf(fmaf(pa.w, sc[kb + 3], sb[kb + 3]), 0.f);
        }
        pb = *(const float4*)(W + (size_t)(k0 + bk) * HD + bn0);
        if (hldr)
            ph = *(const float4*)(fw + ((size_t)layer * HD + k0 + hkr) * CD + hnc);
    };
    auto store_slab = [&](int buf) {
        float av[4] = {pa.x, pa.y, pa.z, pa.w};
        __half ah4[4], al4[4];
#pragma unroll
        for (int j = 0; j < 4; j++) {
            ah4[j] = __float2half_rn(av[j]);
            al4[j] = __float2half_rn(av[j] - __half2float(ah4[j]));
        }
        *(__half2*)&As2[buf][ar][akq]          = *(__half2*)&ah4[0];
        *(__half2*)&As2[buf][ar][akq + 2]      = *(__half2*)&ah4[2];
        *(__half2*)&As2[buf][ar][16 + akq]     = *(__half2*)&al4[0];
        *(__half2*)&As2[buf][ar][16 + akq + 2] = *(__half2*)&al4[2];
        float bv[4] = {pb.x, pb.y, pb.z, pb.w};
        __half bh4[4], bl4[4];
#pragma unroll
        for (int j = 0; j < 4; j++) {
            bh4[j] = __float2half_rn(bv[j]);
            bl4[j] = __float2half_rn(bv[j] - __half2float(bh4[j]));
        }
        *(__half2*)&Bs2[buf][bk][bn0]           = *(__half2*)&bh4[0];
        *(__half2*)&Bs2[buf][bk][bn0 + 2]       = *(__half2*)&bh4[2];
        *(__half2*)&Bs2[buf][bk][136 + bn0]     = *(__half2*)&bl4[0];
        *(__half2*)&Bs2[buf][bk][136 + bn0 + 2] = *(__half2*)&bl4[2];
        if (hldr) {
            float hv4[4] = {ph.x, ph.y, ph.z, ph.w};
            __half hh4[4];
#pragma unroll
            for (int j = 0; j < 4; j++) hh4[j] = __float2half_rn(hv4[j]);
            *(__half2*)&Hh[buf][hkr][hnc]     = *(__half2*)&hh4[0];
            *(__half2*)&Hh[buf][hkr][hnc + 2] = *(__half2*)&hh4[2];
        }
    };

    load_slab(0);
    store_slab(0);
    __syncthreads();

#pragma unroll
    for (int ks = 0; ks < 8; ks++) {
        int buf = ks & 1;
        if (ks < 7) load_slab(ks + 1);
        unsigned ah[2][4], al[2][4];
        unsigned abufoff = (unsigned)buf * 128u * 40u * 2u;
#pragma unroll
        for (int mi = 0; mi < 2; mi++) {
            int m0 = wr + mi * 16;
            unsigned abase = a_sbase + abufoff +
                ((unsigned)((m0 + la_row) * 40 + la_k8)) * 2u;
            ldsm_x4(ah[mi][0], ah[mi][1], ah[mi][2], ah[mi][3], abase);
            ldsm_x4(al[mi][0], al[mi][1], al[mi][2], al[mi][3], abase + 16u * 2u);
        }
        unsigned bh[4][2], bl[4][2];
        unsigned bufoff = (unsigned)buf * 16u * 264u * 2u;
#pragma unroll
        for (int p = 0; p < 2; p++) {
            unsigned addr_hi = b_sbase + bufoff +
                ((unsigned)(ld_k * 264 + wc + p * 16 + ld_n8)) * 2u;
            ldsm_x4_t(bh[2 * p][0], bh[2 * p][1], bh[2 * p + 1][0], bh[2 * p + 1][1], addr_hi);
            ldsm_x4_t(bl[2 * p][0], bl[2 * p][1], bl[2 * p + 1][0], bl[2 * p + 1][1],
                      addr_hi + 136u * 2u);
        }
#pragma unroll
        for (int mi = 0; mi < 2; mi++)
#pragma unroll
            for (int ni = 0; ni < 4; ni++) {
                mma_f16(acc[mi][ni], ah[mi], bh[ni]);
                mma_f16(acc[mi][ni], ah[mi], bl[ni]);
                mma_f16(acc[mi][ni], al[mi], bh[ni]);
            }
        {
            unsigned hbuf = (unsigned)buf * 16u * 56u * 2u;
            unsigned hb[2];
            unsigned haddr = h_sbase + hbuf +
                ((unsigned)(((lane & 7) + ((lt & 1) ? 8 : 0)) * 56 + hc * 8)) * 2u;
            ldsm_x2_t(hb[0], hb[1], haddr);
#pragma unroll
            for (int mi = 0; mi < 2; mi++) {
                mma_f16(acch[0][mi], ah[mi], hb);
                mma_f16(acch[0][mi], al[mi], hb);
            }
            if (hc == 3) {
                unsigned hb4r[2];
                unsigned haddr4 = h_sbase + hbuf +
                    ((unsigned)(((lane & 7) + ((lt & 1) ? 8 : 0)) * 56 + 32)) * 2u;
                ldsm_x2_t(hb4r[0], hb4r[1], haddr4);
#pragma unroll
                for (int mi = 0; mi < 2; mi++) {
                    mma_f16(acch[1][mi], ah[mi], hb4r);
                    mma_f16(acch[1][mi], al[mi], hb4r);
                }
            }
        }
        if (ks < 7) {
            store_slab(buf ^ 1);
            __syncthreads();
        }
    }
#pragma unroll
    for (int mi = 0; mi < 2; mi++) {
#pragma unroll
        for (int ni = 0; ni < 4; ni++) {
            int r = row0 + wr + mi * 16 + g4;
            int c = wc + ni * 8 + t4 * 2;
            if (r < n)
                *(__half2*)(g_xw + (size_t)r * HD + c) =
                    __floats2half2_rn(acc[mi][ni][0], acc[mi][ni][1]);
            if (r + 8 < n)
                *(__half2*)(g_xw + (size_t)(r + 8) * HD + c) =
                    __floats2half2_rn(acc[mi][ni][2], acc[mi][ni][3]);
        }
    }
    int nslots = (hc == 3) ? 2 : 1;
    for (int s = 0; s < nslots; s++) {
        int tile = (s == 0) ? hc : 4;
        int c = tile * 8 + t4 * 2;
#pragma unroll
        for (int mi = 0; mi < 2; mi++) {
#pragma unroll
            for (int half = 0; half < 2; half++) {
                int r = row0 + wr + mi * 16 + half * 8 + g4;
                if (r < n) {
                    float2 val = make_float2(acch[s][mi][half * 2 + 0],
                                             acch[s][mi][half * 2 + 1]);
                    float2* p = (float2*)(g_out + (size_t)r * CD + c);
                    if (layer == 0) {
                        *p = val;
                    } else {
                        float2 o = *p;
                        *p = make_float2(o.x + val.x, o.y + val.y);
                    }
                }
            }
        }
    }
}

// ---------------------------------------------------------------------------
// Aggregation: warp per node; lane owns 4 columns; unroll-8 fp16 gather with
// INTERLEAVED edge records (one LDG.64 per edge instead of 2x LDG.32).
__global__ __launch_bounds__(256) void k_agg(int layer, const float* __restrict__ convb,
                                             const float* __restrict__ bn_g,
                                             const float* __restrict__ bn_b, int n) {
    __shared__ float s_sum[128], s_sq[128];
    __shared__ int s_last;
    int tid = threadIdx.x;
    if (tid < 128) { s_sum[tid] = 0.f; s_sq[tid] = 0.f; }
    __syncthreads();

    int lane = tid & 31;
    int warp = tid >> 5;
    int c4 = lane * 4;
    float4 b4 = *(const float4*)(convb + c4);
    float* out = g_agg[layer];

    int gw = blockIdx.x * 8 + warp;
    int nw = gridDim.x * 8;

    float ls0 = 0.f, ls1 = 0.f, ls2 = 0.f, ls3 = 0.f;
    float lq0 = 0.f, lq1 = 0.f, lq2 = 0.f, lq3 = 0.f;

    for (int v = gw; v < n; v += nw) {
        int r0 = g_off[v], r1 = g_off[v + 1];
        float dv = g_dinv[v];
        unsigned long long p0 = 0ull, p1 = 0ull;
        int j = r0;
        for (; j + 7 < r1; j += 8) {
            int2 ed[8];
#pragma unroll
            for (int u = 0; u < 8; u++) ed[u] = g_edge[j + u];
            uint2 hx[8];
#pragma unroll
            for (int u = 0; u < 8; u++)
                hx[u] = *(const uint2*)(g_xw + (size_t)ed[u].x * HD + c4);
#pragma unroll
            for (int u = 0; u < 8; u++) {
                float2 f0 = __half22float2(*(__half2*)&hx[u].x);
                float2 f1 = __half22float2(*(__half2*)&hx[u].y);
                float w = __int_as_float(ed[u].y);
                unsigned long long wd = pk2(w, w);
                fma2(p0, wd, pk2(f0.x, f0.y));
                fma2(p1, wd, pk2(f1.x, f1.y));
            }
        }
        for (; j < r1; j++) {
            int2 ed = g_edge[j];
            uint2 hx = *(const uint2*)(g_xw + (size_t)ed.x * HD + c4);
            float2 f0 = __half22float2(*(__half2*)&hx.x);
            float2 f1 = __half22float2(*(__half2*)&hx.y);
            float w = __int_as_float(ed.y);
            unsigned long long wd0 = pk2(w, w);
            fma2(p0, wd0, pk2(f0.x, f0.y)); fma2(p1, wd0, pk2(f1.x, f1.y));
        }
        float2 e0 = up2(p0), e1 = up2(p1);
        uint2 hxs = *(const uint2*)(g_xw + (size_t)v * HD + c4);
        float2 xs0 = __half22float2(*(__half2*)&hxs.x);
        float2 xs1 = __half22float2(*(__half2*)&hxs.y);
        float t2 = 2.f * dv * dv;
        float a0 = fmaf(dv, e0.x, fmaf(t2, xs0.x, b4.x));
        float a1 = fmaf(dv, e0.y, fmaf(t2, xs0.y, b4.y));
        float a2 = fmaf(dv, e1.x, fmaf(t2, xs1.x, b4.z));
        float a3 = fmaf(dv, e1.y, fmaf(t2, xs1.y, b4.w));
        *(float4*)(out + (size_t)v * HD + c4) = make_float4(a0, a1, a2, a3);
        ls0 += a0; ls1 += a1; ls2 += a2; ls3 += a3;
        lq0 = fmaf(a0, a0, lq0); lq1 = fmaf(a1, a1, lq1);
        lq2 = fmaf(a2, a2, lq2); lq3 = fmaf(a3, a3, lq3);
    }
    atomicAdd(&s_sum[c4 + 0], ls0); atomicAdd(&s_sum[c4 + 1], ls1);
    atomicAdd(&s_sum[c4 + 2], ls2); atomicAdd(&s_sum[c4 + 3], ls3);
    atomicAdd(&s_sq[c4 + 0], lq0);  atomicAdd(&s_sq[c4 + 1], lq1);
    atomicAdd(&s_sq[c4 + 2], lq2);  atomicAdd(&s_sq[c4 + 3], lq3);
    __syncthreads();
    if (tid < 128) {
        atomicAdd(&g_stats[layer][tid], s_sum[tid]);
        atomicAdd(&g_stats[layer][128 + tid], s_sq[tid]);
    }
    __threadfence();
    __syncthreads();
    if (tid == 0) {
        int p = atomicAdd(&g_done[layer], 1);
        s_last = (p == (int)gridDim.x - 1);
    }
    __syncthreads();
    if (s_last && tid < 128) {
        __threadfence();
        float sum = g_stats[layer][tid];
        float sq  = g_stats[layer][tid + 128];
        g_stats[layer][tid] = 0.f;
        g_stats[layer][tid + 128] = 0.f;
        if (tid == 0) g_done[layer] = 0;
        float inv_n = 1.0f / (float)n;
        float mean = sum * inv_n;
        float var  = fmaxf(sq * inv_n - mean * mean, 0.f);
        float s = bn_g[layer * HD + tid] * rsqrtf(var + 1e-5f);
        g_scale[layer][tid] = s;
        g_sbias[layer][tid] = bn_b[layer * HD + tid] - mean * s;
    }
}

// ---------------------------------------------------------------------------
// Final head: T = relu_bn(g_agg[NLAY-1]) @ fc_w[NLAY]  (K=128 only),
// out = log_softmax(g_out + T + sum_bias). Single-pass tf32. (unchanged)
__global__ __launch_bounds__(256, 2) void k_final(const float* __restrict__ fw,
                                                  const float* __restrict__ fb,
                                                  float* __restrict__ outp, int n) {
    __shared__ __align__(16) float As[2][256][20];
    __shared__ __align__(16) float Bs[2][16][40];
    __shared__ float bsum[40];
    int tid = threadIdx.x;
    int lane = tid & 31, wid = tid >> 5;
    int g4 = lane >> 2, t4 = lane & 3;
    int wr = wid * 32;
    int row0 = blockIdx.x * 256;
    int gr = row0 + tid;
    bool bldr = (tid < 160);
    int bkr = tid / 10, bnc = (tid % 10) * 4;
    const float* A  = g_agg[NLAY - 1];
    const float* sc = g_scale[NLAY - 1];
    const float* sb = g_sbias[NLAY - 1];

    if (tid < 40) {
        float b = 0.f;
        for (int i = 0; i < NLAY + 1; i++) b += fb[i * CD + tid];
        bsum[tid] = b;
    }

    float acc[2][5][4];
#pragma unroll
    for (int mi = 0; mi < 2; mi++)
#pragma unroll
        for (int ni = 0; ni < 5; ni++)
#pragma unroll
            for (int q = 0; q < 4; q++) acc[mi][ni][q] = 0.f;

    float4 pa[4], pbv;
    auto load_slab = [&](int s) {
        int k0 = s * 16;
#pragma unroll
        for (int h = 0; h < 4; h++) pa[h] = make_float4(0.f, 0.f, 0.f, 0.f);
        if (gr < n) {
#pragma unroll
            for (int h = 0; h < 4; h++)
                pa[h] = *(const float4*)(A + (size_t)gr * HD + k0 + h * 4);
        }
#pragma unroll
        for (int h = 0; h < 4; h++) {
            int kk = k0 + h * 4;
            float* p = (float*)&pa[h];
            p[0] = fmaxf(fmaf(p[0], sc[kk + 0], sb[kk + 0]), 0.f);
            p[1] = fmaxf(fmaf(p[1], sc[kk + 1], sb[kk + 1]), 0.f);
            p[2] = fmaxf(fmaf(p[2], sc[kk + 2], sb[kk + 2]), 0.f);
            p[3] = fmaxf(fmaf(p[3], sc[kk + 3], sb[kk + 3]), 0.f);
        }
        if (bldr)
            pbv = *(const float4*)(fw + ((size_t)NLAY * HD + k0 + bkr) * CD + bnc);
    };
    auto store_slab = [&](int buf) {
#pragma unroll
        for (int h = 0; h < 4; h++) *(float4*)&As[buf][tid][h * 4] = pa[h];
        if (bldr) *(float4*)&Bs[buf][bkr][bnc] = pbv;
    };

    load_slab(0);
    store_slab(0);
    __syncthreads();

#pragma unroll
    for (int slab = 0; slab < 8; slab++) {
        int buf = slab & 1;
        if (slab < 7) load_slab(slab + 1);
#pragma unroll
        for (int kk = 0; kk < 2; kk++) {
            int kb = kk * 8;
            unsigned ahi[2][4], bhi[5][2];
#pragma unroll
            for (int mi = 0; mi < 2; mi++) {
                int m0 = wr + mi * 16 + g4;
                ahi[mi][0] = tf32_cvt(As[buf][m0][kb + t4]);
                ahi[mi][1] = tf32_cvt(As[buf][m0 + 8][kb + t4]);
                ahi[mi][2] = tf32_cvt(As[buf][m0][kb + 4 + t4]);
                ahi[mi][3] = tf32_cvt(As[buf][m0 + 8][kb + 4 + t4]);
            }
#pragma unroll
            for (int ni = 0; ni < 5; ni++) {
                int nn = ni * 8 + g4;
                bhi[ni][0] = tf32_cvt(Bs[buf][kb + t4][nn]);
                bhi[ni][1] = tf32_cvt(Bs[buf][kb + 4 + t4][nn]);
            }
#pragma unroll
            for (int mi = 0; mi < 2; mi++)
#pragma unroll
                for (int ni = 0; ni < 5; ni++)
                    mma_tf32(acc[mi][ni], ahi[mi], bhi[ni]);
        }
        if (slab < 7) {
            store_slab(buf ^ 1);
            __syncthreads();
        }
    }

#pragma unroll
    for (int mi = 0; mi < 2; mi++) {
#pragma unroll
        for (int half = 0; half < 2; half++) {
            int r = row0 + wr + mi * 16 + half * 8 + g4;
            float v[5][2];
#pragma unroll
            for (int ni = 0; ni < 5; ni++) {
                int c = ni * 8 + t4 * 2;
                float2 o = make_float2(0.f, 0.f);
                if (r < n) o = *(const float2*)(g_out + (size_t)r * CD + c);
                v[ni][0] = acc[mi][ni][half * 2 + 0] + o.x + bsum[c];
                v[ni][1] = acc[mi][ni][half * 2 + 1] + o.y + bsum[c + 1];
            }
            float mx = v[0][0];
#pragma unroll
            for (int ni = 0; ni < 5; ni++) {
                mx = fmaxf(mx, v[ni][0]);
                mx = fmaxf(mx, v[ni][1]);
            }
            mx = fmaxf(mx, __shfl_xor_sync(0xffffffffu, mx, 1));
            mx = fmaxf(mx, __shfl_xor_sync(0xffffffffu, mx, 2));
            float s = 0.f;
#pragma unroll
            for (int ni = 0; ni < 5; ni++)
                s += expf(v[ni][0] - mx) + expf(v[ni][1] - mx);
            s += __shfl_xor_sync(0xffffffffu, s, 1);
            s += __shfl_xor_sync(0xffffffffu, s, 2);
            float ls = mx + logf(s);
            if (r < n) {
#pragma unroll
                for (int ni = 0; ni < 5; ni++)
                    *(float2*)(outp + (size_t)r * CD + ni * 8 + t4 * 2) =
                        make_float2(v[ni][0] - ls, v[ni][1] - ls);
            }
        }
    }
}

// ---------------------------------------------------------------------------
// Side stream + events for overlapping the graph-prep chain with gemm layer 0.
static cudaStream_t g_s2 = 0;
static cudaEvent_t  g_ev_fork = 0, g_ev_join = 0;

extern "C" void kernel_launch(void* const* d_in, const int* in_sizes, int n_in,
                              void* d_out, int out_size) {
    const float* x      = (const float*)d_in[0];
    const int*   ei     = (const int*)d_in[1];
    const float* conv_w = (const float*)d_in[2];
    const float* conv_b = (const float*)d_in[3];
    const float* bn_g   = (const float*)d_in[4];
    const float* bn_b   = (const float*)d_in[5];
    const float* fc_w   = (const float*)d_in[6];
    const float* fc_b   = (const float*)d_in[7];
    int n = in_sizes[0] / FD;
    int e = in_sizes[1] / 2;
    const int* src = ei;
    const int* dst = ei + e;

    if (g_s2 == 0) {
        cudaStreamCreateWithFlags(&g_s2, cudaStreamNonBlocking);
        cudaEventCreateWithFlags(&g_ev_fork, cudaEventDisableTiming);
        cudaEventCreateWithFlags(&g_ev_join, cudaEventDisableTiming);
    }

    int gblocks = (n + 127) / 128;
    int ehalf = e / 2;

    // fork: graph prep on side stream, concurrent with layer-0 GEMM + head
    cudaEventRecord(g_ev_fork, 0);
    cudaStreamWaitEvent(g_s2, g_ev_fork, 0);
    k_hist<<<(ehalf + 255) / 256, 256, 0, g_s2>>>(dst, 0, ehalf);
    k_hist<<<(e - ehalf + 255) / 256, 256, 0, g_s2>>>(dst, ehalf, e);
    k_scan<<<1, 1024, 0, g_s2>>>(n);
    k_fill<<<(e + 255) / 256, 256, 0, g_s2>>>(src, dst, e);
    cudaEventRecord(g_ev_join, g_s2);

    k_gemm<<<gblocks, 512>>>(x, conv_w, fc_w, 0, n);

    cudaStreamWaitEvent(0, g_ev_join, 0);
    k_agg<<<1184, 256>>>(0, conv_b, bn_g, bn_b, n);

    for (int l = 1; l < NLAY; l++) {
        k_gemm<<<gblocks, 512>>>(x, conv_w + (size_t)l * FD * HD, fc_w, l, n);
        k_agg<<<1184, 256>>>(l, conv_b + (size_t)l * HD, bn_g, bn_b, n);
    }
    k_final<<<(n + 255) / 256, 256>>>(fc_w, fc_b, (float*)d_out, n);
}

// round 17
// speedup vs baseline: 1.2680x; 1.0136x over previous
#include <cuda_runtime.h>
#include <cuda_fp16.h>
#include <math.h>

#define NMAX 100000
#define EMAX 1600000
#define FD 128
#define HD 128
#define CD 40
#define NLAY 4

// ---- static device scratch ----
// Invariant: g_cnt, g_stats, g_done are zero at entry of every kernel_launch
// call (zero at module load; each call re-zeroes them after use).
__device__ __half g_xw[(size_t)NMAX * HD];          // fp16 conv output
__device__ __half g_agg[NLAY][(size_t)NMAX * HD];   // fp16 pre-BN aggregated
__device__ float g_out[(size_t)NMAX * CD];
__device__ int   g_cnt[NMAX];
__device__ float g_dinv[NMAX];
__device__ int   g_off[NMAX + 1];
__device__ int   g_cur[NMAX];
__device__ int2  g_edge[EMAX];                 // interleaved {src, dinv[src] bits}
__device__ float g_stats[NLAY][2 * HD];
__device__ float g_scale[NLAY][HD];
__device__ float g_sbias[NLAY][HD];
__device__ int   g_done[NLAY];

// ---- packed f32x2 helpers ----
__device__ __forceinline__ unsigned long long pk2(float lo, float hi) {
    unsigned long long r;
    asm("mov.b64 %0, {%1, %2};" : "=l"(r) : "f"(lo), "f"(hi));
    return r;
}
__device__ __forceinline__ void fma2(unsigned long long& d,
                                     unsigned long long a, unsigned long long b) {
    asm("fma.rn.f32x2 %0, %1, %2, %0;" : "+l"(d) : "l"(a), "l"(b));
}
__device__ __forceinline__ float2 up2(unsigned long long v) {
    float2 r;
    asm("mov.b64 {%0, %1}, %2;" : "=f"(r.x), "=f"(r.y) : "l"(v));
    return r;
}

// ---- tf32 helpers (k_final) ----
__device__ __forceinline__ unsigned tf32_cvt(float f) {
    unsigned r;
    asm("cvt.rna.tf32.f32 %0, %1;" : "=r"(r) : "f"(f));
    return r;
}
__device__ __forceinline__ void mma_tf32(float* c, const unsigned* a, const unsigned* b) {
    asm("mma.sync.aligned.m16n8k8.row.col.f32.tf32.tf32.f32 "
        "{%0,%1,%2,%3}, {%4,%5,%6,%7}, {%8,%9}, {%0,%1,%2,%3};"
        : "+f"(c[0]), "+f"(c[1]), "+f"(c[2]), "+f"(c[3])
        : "r"(a[0]), "r"(a[1]), "r"(a[2]), "r"(a[3]), "r"(b[0]), "r"(b[1]));
}

// ---- fp16 m16n8k16 MMA (fp32 accum) + ldmatrix ----
__device__ __forceinline__ void mma_f16(float* c, const unsigned* a, const unsigned* b) {
    asm("mma.sync.aligned.m16n8k16.row.col.f32.f16.f16.f32 "
        "{%0,%1,%2,%3}, {%4,%5,%6,%7}, {%8,%9}, {%0,%1,%2,%3};"
        : "+f"(c[0]), "+f"(c[1]), "+f"(c[2]), "+f"(c[3])
        : "r"(a[0]), "r"(a[1]), "r"(a[2]), "r"(a[3]), "r"(b[0]), "r"(b[1]));
}
__device__ __forceinline__ void ldsm_x4(unsigned& r0, unsigned& r1,
                                        unsigned& r2, unsigned& r3, unsigned addr) {
    asm volatile("ldmatrix.sync.aligned.m8n8.x4.shared.b16 {%0,%1,%2,%3}, [%4];"
                 : "=r"(r0), "=r"(r1), "=r"(r2), "=r"(r3) : "r"(addr));
}
__device__ __forceinline__ void ldsm_x4_t(unsigned& r0, unsigned& r1,
                                          unsigned& r2, unsigned& r3, unsigned addr) {
    asm volatile("ldmatrix.sync.aligned.m8n8.x4.trans.shared.b16 {%0,%1,%2,%3}, [%4];"
                 : "=r"(r0), "=r"(r1), "=r"(r2), "=r"(r3) : "r"(addr));
}
__device__ __forceinline__ void ldsm_x2_t(unsigned& r0, unsigned& r1, unsigned addr) {
    asm volatile("ldmatrix.sync.aligned.m8n8.x2.trans.shared.b16 {%0,%1}, [%2];"
                 : "=r"(r0), "=r"(r1) : "r"(addr));
}

// ---------------------------------------------------------------------------
__global__ void k_hist(const int* __restrict__ dst, int base, int e) {
    int i = base + blockIdx.x * blockDim.x + threadIdx.x;
    if (i < e) atomicAdd(&g_cnt[dst[i]], 1);
}

__global__ void k_scan(int n) {
    __shared__ int sp[1024];
    int t = threadIdx.x;
    int chunk = (n + 1023) >> 10;
    int beg = t * chunk;
    int end = min(beg + chunk, n);
    int s = 0;
    for (int j = beg; j < end; j++) s += g_cnt[j];
    sp[t] = s;
    __syncthreads();
    for (int d = 1; d < 1024; d <<= 1) {
        int tmp = (t >= d) ? sp[t - d] : 0;
        __syncthreads();
        sp[t] += tmp;
        __syncthreads();
    }
    int base = sp[t] - s;
    for (int j = beg; j < end; j++) {
        int c = g_cnt[j];
        g_cnt[j] = 0;  // self-reset
        g_off[j] = base;
        g_cur[j] = base;
        g_dinv[j] = rsqrtf((float)c + 2.0f);
        base += c;
    }
    if (end == n) g_off[n] = base;
}

__global__ void k_fill(const int* __restrict__ src, const int* __restrict__ dst, int e) {
    int i = blockIdx.x * blockDim.x + threadIdx.x;
    if (i < e) {
        int d = dst[i];
        int s = src[i];
        int p = atomicAdd(&g_cur[d], 1);
        g_edge[p] = make_int2(s, __float_as_int(g_dinv[s]));
    }
}

// ---------------------------------------------------------------------------
// Conv SGEMM via SPLIT-FP16 m16n8k16 (3 cross terms) fused with class head.
// A source: x (fp32, layer 0) or fp16 g_agg[layer-1] with BN+ReLU on load.
__global__ __launch_bounds__(512, 1) void k_gemm(const float* __restrict__ x,
                                                 const float* __restrict__ W,
                                                 const float* __restrict__ fw,
                                                 int layer, int n) {
    __shared__ __align__(16) __half As2[2][128][40];
    __shared__ __align__(16) __half Bs2[2][16][264];
    __shared__ __align__(16) __half Hh[2][16][56];
    const __half* Ah = (layer > 0) ? g_agg[layer - 1] : 0;
    const float* sc = (layer > 0) ? g_scale[layer - 1] : 0;
    const float* sb = (layer > 0) ? g_sbias[layer - 1] : 0;
    int tid = threadIdx.x;
    int lane = tid & 31, wid = tid >> 5;
    int g4 = lane >> 2, t4 = lane & 3;
    int wr = (wid >> 2) * 32, wc = (wid & 3) * 32;
    int hc = wid & 3;
    int ar = tid >> 2, akq = (tid & 3) * 4;
    int bk = tid >> 5, bn0 = (tid & 31) * 4;
    bool hldr = (tid < 160);
    int hkr = tid / 10, hnc = (tid % 10) * 4;
    int row0 = blockIdx.x * 128;
    int gr = row0 + ar;

    int lt = lane >> 3;
    int ld_k = ((lt & 1) ? 8 : 0) + (lane & 7);
    int ld_n8 = (lt >> 1) * 8;
    int la_row = lane & 15;
    int la_k8  = (lane >> 4) * 8;
    unsigned a_sbase = (unsigned)__cvta_generic_to_shared(&As2[0][0][0]);
    unsigned b_sbase = (unsigned)__cvta_generic_to_shared(&Bs2[0][0][0]);
    unsigned h_sbase = (unsigned)__cvta_generic_to_shared(&Hh[0][0][0]);

    float acc[2][4][4];
#pragma unroll
    for (int mi = 0; mi < 2; mi++)
#pragma unroll
        for (int ni = 0; ni < 4; ni++)
#pragma unroll
            for (int q = 0; q < 4; q++) acc[mi][ni][q] = 0.f;
    float acch[2][2][4];
#pragma unroll
    for (int s = 0; s < 2; s++)
#pragma unroll
        for (int mi = 0; mi < 2; mi++)
#pragma unroll
            for (int q = 0; q < 4; q++) acch[s][mi][q] = 0.f;

    float4 pa, pb, ph;
    auto load_slab = [&](int s) {
        int k0 = s * 16;
        pa = make_float4(0.f, 0.f, 0.f, 0.f);
        if (layer == 0) {
            if (gr < n) pa = *(const float4*)(x + (size_t)gr * HD + k0 + akq);
        } else {
            if (gr < n) {
                uint2 h = *(const uint2*)(Ah + (size_t)gr * HD + k0 + akq);
                float2 f0 = __half22float2(*(__half2*)&h.x);
                float2 f1 = __half22float2(*(__half2*)&h.y);
                pa = make_float4(f0.x, f0.y, f1.x, f1.y);
            }
            int kb = k0 + akq;
            pa.x = fmaxf(fmaf(pa.x, sc[kb + 0], sb[kb + 0]), 0.f);
            pa.y = fmaxf(fmaf(pa.y, sc[kb + 1], sb[kb + 1]), 0.f);
            pa.z = fmaxf(fmaf(pa.z, sc[kb + 2], sb[kb + 2]), 0.f);
            pa.w = fmaxf(fmaf(pa.w, sc[kb + 3], sb[kb + 3]), 0.f);
        }
        pb = *(const float4*)(W + (size_t)(k0 + bk) * HD + bn0);
        if (hldr)
            ph = *(const float4*)(fw + ((size_t)layer * HD + k0 + hkr) * CD + hnc);
    };
    auto store_slab = [&](int buf) {
        float av[4] = {pa.x, pa.y, pa.z, pa.w};
        __half ah4[4], al4[4];
#pragma unroll
        for (int j = 0; j < 4; j++) {
            ah4[j] = __float2half_rn(av[j]);
            al4[j] = __float2half_rn(av[j] - __half2float(ah4[j]));
        }
        *(__half2*)&As2[buf][ar][akq]          = *(__half2*)&ah4[0];
        *(__half2*)&As2[buf][ar][akq + 2]      = *(__half2*)&ah4[2];
        *(__half2*)&As2[buf][ar][16 + akq]     = *(__half2*)&al4[0];
        *(__half2*)&As2[buf][ar][16 + akq + 2] = *(__half2*)&al4[2];
        float bv[4] = {pb.x, pb.y, pb.z, pb.w};
        __half bh4[4], bl4[4];
#pragma unroll
        for (int j = 0; j < 4; j++) {
            bh4[j] = __float2half_rn(bv[j]);
            bl4[j] = __float2half_rn(bv[j] - __half2float(bh4[j]));
        }
        *(__half2*)&Bs2[buf][bk][bn0]           = *(__half2*)&bh4[0];
        *(__half2*)&Bs2[buf][bk][bn0 + 2]       = *(__half2*)&bh4[2];
        *(__half2*)&Bs2[buf][bk][136 + bn0]     = *(__half2*)&bl4[0];
        *(__half2*)&Bs2[buf][bk][136 + bn0 + 2] = *(__half2*)&bl4[2];
        if (hldr) {
            float hv4[4] = {ph.x, ph.y, ph.z, ph.w};
            __half hh4[4];
#pragma unroll
            for (int j = 0; j < 4; j++) hh4[j] = __float2half_rn(hv4[j]);
            *(__half2*)&Hh[buf][hkr][hnc]     = *(__half2*)&hh4[0];
            *(__half2*)&Hh[buf][hkr][hnc + 2] = *(__half2*)&hh4[2];
        }
    };

    load_slab(0);
    store_slab(0);
    __syncthreads();

#pragma unroll
    for (int ks = 0; ks < 8; ks++) {
        int buf = ks & 1;
        if (ks < 7) load_slab(ks + 1);
        unsigned ah[2][4], al[2][4];
        unsigned abufoff = (unsigned)buf * 128u * 40u * 2u;
#pragma unroll
        for (int mi = 0; mi < 2; mi++) {
            int m0 = wr + mi * 16;
            unsigned abase = a_sbase + abufoff +
                ((unsigned)((m0 + la_row) * 40 + la_k8)) * 2u;
            ldsm_x4(ah[mi][0], ah[mi][1], ah[mi][2], ah[mi][3], abase);
            ldsm_x4(al[mi][0], al[mi][1], al[mi][2], al[mi][3], abase + 16u * 2u);
        }
        unsigned bh[4][2], bl[4][2];
        unsigned bufoff = (unsigned)buf * 16u * 264u * 2u;
#pragma unroll
        for (int p = 0; p < 2; p++) {
            unsigned addr_hi = b_sbase + bufoff +
                ((unsigned)(ld_k * 264 + wc + p * 16 + ld_n8)) * 2u;
            ldsm_x4_t(bh[2 * p][0], bh[2 * p][1], bh[2 * p + 1][0], bh[2 * p + 1][1], addr_hi);
            ldsm_x4_t(bl[2 * p][0], bl[2 * p][1], bl[2 * p + 1][0], bl[2 * p + 1][1],
                      addr_hi + 136u * 2u);
        }
#pragma unroll
        for (int mi = 0; mi < 2; mi++)
#pragma unroll
            for (int ni = 0; ni < 4; ni++) {
                mma_f16(acc[mi][ni], ah[mi], bh[ni]);
                mma_f16(acc[mi][ni], ah[mi], bl[ni]);
                mma_f16(acc[mi][ni], al[mi], bh[ni]);
            }
        {
            unsigned hbuf = (unsigned)buf * 16u * 56u * 2u;
            unsigned hb[2];
            unsigned haddr = h_sbase + hbuf +
                ((unsigned)(((lane & 7) + ((lt & 1) ? 8 : 0)) * 56 + hc * 8)) * 2u;
            ldsm_x2_t(hb[0], hb[1], haddr);
#pragma unroll
            for (int mi = 0; mi < 2; mi++) {
                mma_f16(acch[0][mi], ah[mi], hb);
                mma_f16(acch[0][mi], al[mi], hb);
            }
            if (hc == 3) {
                unsigned hb4r[2];
                unsigned haddr4 = h_sbase + hbuf +
                    ((unsigned)(((lane & 7) + ((lt & 1) ? 8 : 0)) * 56 + 32)) * 2u;
                ldsm_x2_t(hb4r[0], hb4r[1], haddr4);
#pragma unroll
                for (int mi = 0; mi < 2; mi++) {
                    mma_f16(acch[1][mi], ah[mi], hb4r);
                    mma_f16(acch[1][mi], al[mi], hb4r);
                }
            }
        }
        if (ks < 7) {
            store_slab(buf ^ 1);
            __syncthreads();
        }
    }
#pragma unroll
    for (int mi = 0; mi < 2; mi++) {
#pragma unroll
        for (int ni = 0; ni < 4; ni++) {
            int r = row0 + wr + mi * 16 + g4;
            int c = wc + ni * 8 + t4 * 2;
            if (r < n)
                *(__half2*)(g_xw + (size_t)r * HD + c) =
                    __floats2half2_rn(acc[mi][ni][0], acc[mi][ni][1]);
            if (r + 8 < n)
                *(__half2*)(g_xw + (size_t)(r + 8) * HD + c) =
                    __floats2half2_rn(acc[mi][ni][2], acc[mi][ni][3]);
        }
    }
    int nslots = (hc == 3) ? 2 : 1;
    for (int s = 0; s < nslots; s++) {
        int tile = (s == 0) ? hc : 4;
        int c = tile * 8 + t4 * 2;
#pragma unroll
        for (int mi = 0; mi < 2; mi++) {
#pragma unroll
            for (int half = 0; half < 2; half++) {
                int r = row0 + wr + mi * 16 + half * 8 + g4;
                if (r < n) {
                    float2 val = make_float2(acch[s][mi][half * 2 + 0],
                                             acch[s][mi][half * 2 + 1]);
                    float2* p = (float2*)(g_out + (size_t)r * CD + c);
                    if (layer == 0) {
                        *p = val;
                    } else {
                        float2 o = *p;
                        *p = make_float2(o.x + val.x, o.y + val.y);
                    }
                }
            }
        }
    }
}

// ---------------------------------------------------------------------------
// Aggregation: warp per node; lane owns 4 columns; unroll-8 fp16 gather with
// interleaved edge records. Output stored fp16 (uint2 of 2x half2).
__global__ __launch_bounds__(256) void k_agg(int layer, const float* __restrict__ convb,
                                             const float* __restrict__ bn_g,
                                             const float* __restrict__ bn_b, int n) {
    __shared__ float s_sum[128], s_sq[128];
    __shared__ int s_last;
    int tid = threadIdx.x;
    if (tid < 128) { s_sum[tid] = 0.f; s_sq[tid] = 0.f; }
    __syncthreads();

    int lane = tid & 31;
    int warp = tid >> 5;
    int c4 = lane * 4;
    float4 b4 = *(const float4*)(convb + c4);
    __half* out = g_agg[layer];

    int gw = blockIdx.x * 8 + warp;
    int nw = gridDim.x * 8;

    float ls0 = 0.f, ls1 = 0.f, ls2 = 0.f, ls3 = 0.f;
    float lq0 = 0.f, lq1 = 0.f, lq2 = 0.f, lq3 = 0.f;

    for (int v = gw; v < n; v += nw) {
        int r0 = g_off[v], r1 = g_off[v + 1];
        float dv = g_dinv[v];
        unsigned long long p0 = 0ull, p1 = 0ull;
        int j = r0;
        for (; j + 7 < r1; j += 8) {
            int2 ed[8];
#pragma unroll
            for (int u = 0; u < 8; u++) ed[u] = g_edge[j + u];
            uint2 hx[8];
#pragma unroll
            for (int u = 0; u < 8; u++)
                hx[u] = *(const uint2*)(g_xw + (size_t)ed[u].x * HD + c4);
#pragma unroll
            for (int u = 0; u < 8; u++) {
                float2 f0 = __half22float2(*(__half2*)&hx[u].x);
                float2 f1 = __half22float2(*(__half2*)&hx[u].y);
                float w = __int_as_float(ed[u].y);
                unsigned long long wd = pk2(w, w);
                fma2(p0, wd, pk2(f0.x, f0.y));
                fma2(p1, wd, pk2(f1.x, f1.y));
            }
        }
        for (; j < r1; j++) {
            int2 ed = g_edge[j];
            uint2 hx = *(const uint2*)(g_xw + (size_t)ed.x * HD + c4);
            float2 f0 = __half22float2(*(__half2*)&hx.x);
            float2 f1 = __half22float2(*(__half2*)&hx.y);
            float w = __int_as_float(ed.y);
            unsigned long long wd0 = pk2(w, w);
            fma2(p0, wd0, pk2(f0.x, f0.y)); fma2(p1, wd0, pk2(f1.x, f1.y));
        }
        float2 e0 = up2(p0), e1 = up2(p1);
        uint2 hxs = *(const uint2*)(g_xw + (size_t)v * HD + c4);
        float2 xs0 = __half22float2(*(__half2*)&hxs.x);
        float2 xs1 = __half22float2(*(__half2*)&hxs.y);
        float t2 = 2.f * dv * dv;
        float a0 = fmaf(dv, e0.x, fmaf(t2, xs0.x, b4.x));
        float a1 = fmaf(dv, e0.y, fmaf(t2, xs0.y, b4.y));
        float a2 = fmaf(dv, e1.x, fmaf(t2, xs1.x, b4.z));
        float a3 = fmaf(dv, e1.y, fmaf(t2, xs1.y, b4.w));
        uint2 st;
        *(__half2*)&st.x = __floats2half2_rn(a0, a1);
        *(__half2*)&st.y = __floats2half2_rn(a2, a3);
        *(uint2*)(out + (size_t)v * HD + c4) = st;
        ls0 += a0; ls1 += a1; ls2 += a2; ls3 += a3;
        lq0 = fmaf(a0, a0, lq0); lq1 = fmaf(a1, a1, lq1);
        lq2 = fmaf(a2, a2, lq2); lq3 = fmaf(a3, a3, lq3);
    }
    atomicAdd(&s_sum[c4 + 0], ls0); atomicAdd(&s_sum[c4 + 1], ls1);
    atomicAdd(&s_sum[c4 + 2], ls2); atomicAdd(&s_sum[c4 + 3], ls3);
    atomicAdd(&s_sq[c4 + 0], lq0);  atomicAdd(&s_sq[c4 + 1], lq1);
    atomicAdd(&s_sq[c4 + 2], lq2);  atomicAdd(&s_sq[c4 + 3], lq3);
    __syncthreads();
    if (tid < 128) {
        atomicAdd(&g_stats[layer][tid], s_sum[tid]);
        atomicAdd(&g_stats[layer][128 + tid], s_sq[tid]);
    }
    __threadfence();
    __syncthreads();
    if (tid == 0) {
        int p = atomicAdd(&g_done[layer], 1);
        s_last = (p == (int)gridDim.x - 1);
    }
    __syncthreads();
    if (s_last && tid < 128) {
        __threadfence();
        float sum = g_stats[layer][tid];
        float sq  = g_stats[layer][tid + 128];
        g_stats[layer][tid] = 0.f;
        g_stats[layer][tid + 128] = 0.f;
        if (tid == 0) g_done[layer] = 0;
        float inv_n = 1.0f / (float)n;
        float mean = sum * inv_n;
        float var  = fmaxf(sq * inv_n - mean * mean, 0.f);
        float s = bn_g[layer * HD + tid] * rsqrtf(var + 1e-5f);
        g_scale[layer][tid] = s;
        g_sbias[layer][tid] = bn_b[layer * HD + tid] - mean * s;
    }
}

// ---------------------------------------------------------------------------
// Final head: T = relu_bn(g_agg[NLAY-1]) @ fc_w[NLAY]  (K=128, fp16 A source),
// out = log_softmax(g_out + T + sum_bias). Single-pass tf32.
__global__ __launch_bounds__(256, 2) void k_final(const float* __restrict__ fw,
                                                  const float* __restrict__ fb,
                                                  float* __restrict__ outp, int n) {
    __shared__ __align__(16) float As[2][256][20];
    __shared__ __align__(16) float Bs[2][16][40];
    __shared__ float bsum[40];
    int tid = threadIdx.x;
    int lane = tid & 31, wid = tid >> 5;
    int g4 = lane >> 2, t4 = lane & 3;
    int wr = wid * 32;
    int row0 = blockIdx.x * 256;
    int gr = row0 + tid;
    bool bldr = (tid < 160);
    int bkr = tid / 10, bnc = (tid % 10) * 4;
    const __half* Ah = g_agg[NLAY - 1];
    const float* sc = g_scale[NLAY - 1];
    const float* sb = g_sbias[NLAY - 1];

    if (tid < 40) {
        float b = 0.f;
        for (int i = 0; i < NLAY + 1; i++) b += fb[i * CD + tid];
        bsum[tid] = b;
    }

    float acc[2][5][4];
#pragma unroll
    for (int mi = 0; mi < 2; mi++)
#pragma unroll
        for (int ni = 0; ni < 5; ni++)
#pragma unroll
            for (int q = 0; q < 4; q++) acc[mi][ni][q] = 0.f;

    float4 pa[4], pbv;
    auto load_slab = [&](int s) {
        int k0 = s * 16;
#pragma unroll
        for (int h = 0; h < 4; h++) pa[h] = make_float4(0.f, 0.f, 0.f, 0.f);
        if (gr < n) {
#pragma unroll
            for (int h = 0; h < 4; h++) {
                uint2 hv = *(const uint2*)(Ah + (size_t)gr * HD + k0 + h * 4);
                float2 f0 = __half22float2(*(__half2*)&hv.x);
                float2 f1 = __half22float2(*(__half2*)&hv.y);
                pa[h] = make_float4(f0.x, f0.y, f1.x, f1.y);
            }
        }
#pragma unroll
        for (int h = 0; h < 4; h++) {
            int kk = k0 + h * 4;
            float* p = (float*)&pa[h];
            p[0] = fmaxf(fmaf(p[0], sc[kk + 0], sb[kk + 0]), 0.f);
            p[1] = fmaxf(fmaf(p[1], sc[kk + 1], sb[kk + 1]), 0.f);
            p[2] = fmaxf(fmaf(p[2], sc[kk + 2], sb[kk + 2]), 0.f);
            p[3] = fmaxf(fmaf(p[3], sc[kk + 3], sb[kk + 3]), 0.f);
        }
        if (bldr)
            pbv = *(const float4*)(fw + ((size_t)NLAY * HD + k0 + bkr) * CD + bnc);
    };
    auto store_slab = [&](int buf) {
#pragma unroll
        for (int h = 0; h < 4; h++) *(float4*)&As[buf][tid][h * 4] = pa[h];
        if (bldr) *(float4*)&Bs[buf][bkr][bnc] = pbv;
    };

    load_slab(0);
    store_slab(0);
    __syncthreads();

#pragma unroll
    for (int slab = 0; slab < 8; slab++) {
        int buf = slab & 1;
        if (slab < 7) load_slab(slab + 1);
#pragma unroll
        for (int kk = 0; kk < 2; kk++) {
            int kb = kk * 8;
            unsigned ahi[2][4], bhi[5][2];
#pragma unroll
            for (int mi = 0; mi < 2; mi++) {
                int m0 = wr + mi * 16 + g4;
                ahi[mi][0] = tf32_cvt(As[buf][m0][kb + t4]);
                ahi[mi][1] = tf32_cvt(As[buf][m0 + 8][kb + t4]);
                ahi[mi][2] = tf32_cvt(As[buf][m0][kb + 4 + t4]);
                ahi[mi][3] = tf32_cvt(As[buf][m0 + 8][kb + 4 + t4]);
            }
#pragma unroll
            for (int ni = 0; ni < 5; ni++) {
                int nn = ni * 8 + g4;
                bhi[ni][0] = tf32_cvt(Bs[buf][kb + t4][nn]);
                bhi[ni][1] = tf32_cvt(Bs[buf][kb + 4 + t4][nn]);
            }
#pragma unroll
            for (int mi = 0; mi < 2; mi++)
#pragma unroll
                for (int ni = 0; ni < 5; ni++)
                    mma_tf32(acc[mi][ni], ahi[mi], bhi[ni]);
        }
        if (slab < 7) {
            store_slab(buf ^ 1);
            __syncthreads();
        }
    }

#pragma unroll
    for (int mi = 0; mi < 2; mi++) {
#pragma unroll
        for (int half = 0; half < 2; half++) {
            int r = row0 + wr + mi * 16 + half * 8 + g4;
            float v[5][2];
#pragma unroll
            for (int ni = 0; ni < 5; ni++) {
                int c = ni * 8 + t4 * 2;
                float2 o = make_float2(0.f, 0.f);
                if (r < n) o = *(const float2*)(g_out + (size_t)r * CD + c);
                v[ni][0] = acc[mi][ni][half * 2 + 0] + o.x + bsum[c];
                v[ni][1] = acc[mi][ni][half * 2 + 1] + o.y + bsum[c + 1];
            }
            float mx = v[0][0];
#pragma unroll
            for (int ni = 0; ni < 5; ni++) {
                mx = fmaxf(mx, v[ni][0]);
                mx = fmaxf(mx, v[ni][1]);
            }
            mx = fmaxf(mx, __shfl_xor_sync(0xffffffffu, mx, 1));
            mx = fmaxf(mx, __shfl_xor_sync(0xffffffffu, mx, 2));
            float s = 0.f;
#pragma unroll
            for (int ni = 0; ni < 5; ni++)
                s += expf(v[ni][0] - mx) + expf(v[ni][1] - mx);
            s += __shfl_xor_sync(0xffffffffu, s, 1);
            s += __shfl_xor_sync(0xffffffffu, s, 2);
            float ls = mx + logf(s);
            if (r < n) {
#pragma unroll
                for (int ni = 0; ni < 5; ni++)
                    *(float2*)(outp + (size_t)r * CD + ni * 8 + t4 * 2) =
                        make_float2(v[ni][0] - ls, v[ni][1] - ls);
            }
        }
    }
}

// ---------------------------------------------------------------------------
// Side stream + events for overlapping the graph-prep chain with gemm layer 0.
static cudaStream_t g_s2 = 0;
static cudaEvent_t  g_ev_fork = 0, g_ev_join = 0;

extern "C" void kernel_launch(void* const* d_in, const int* in_sizes, int n_in,
                              void* d_out, int out_size) {
    const float* x      = (const float*)d_in[0];
    const int*   ei     = (const int*)d_in[1];
    const float* conv_w = (const float*)d_in[2];
    const float* conv_b = (const float*)d_in[3];
    const float* bn_g   = (const float*)d_in[4];
    const float* bn_b   = (const float*)d_in[5];
    const float* fc_w   = (const float*)d_in[6];
    const float* fc_b   = (const float*)d_in[7];
    int n = in_sizes[0] / FD;
    int e = in_sizes[1] / 2;
    const int* src = ei;
    const int* dst = ei + e;

    if (g_s2 == 0) {
        cudaStreamCreateWithFlags(&g_s2, cudaStreamNonBlocking);
        cudaEventCreateWithFlags(&g_ev_fork, cudaEventDisableTiming);
        cudaEventCreateWithFlags(&g_ev_join, cudaEventDisableTiming);
    }

    int gblocks = (n + 127) / 128;
    int ehalf = e / 2;

    // fork: graph prep on side stream, concurrent with layer-0 GEMM + head
    cudaEventRecord(g_ev_fork, 0);
    cudaStreamWaitEvent(g_s2, g_ev_fork, 0);
    k_hist<<<(ehalf + 255) / 256, 256, 0, g_s2>>>(dst, 0, ehalf);
    k_hist<<<(e - ehalf + 255) / 256, 256, 0, g_s2>>>(dst, ehalf, e);
    k_scan<<<1, 1024, 0, g_s2>>>(n);
    k_fill<<<(e + 255) / 256, 256, 0, g_s2>>>(src, dst, e);
    cudaEventRecord(g_ev_join, g_s2);

    k_gemm<<<gblocks, 512>>>(x, conv_w, fc_w, 0, n);

    cudaStreamWaitEvent(0, g_ev_join, 0);
    k_agg<<<1184, 256>>>(0, conv_b, bn_g, bn_b, n);

    for (int l = 1; l < NLAY; l++) {
        k_gemm<<<gblocks, 512>>>(x, conv_w + (size_t)l * FD * HD, fc_w, l, n);
        k_agg<<<1184, 256>>>(l, conv_b + (size_t)l * HD, bn_g, bn_b, n);
    }
    k_final<<<(n + 255) / 256, 256>>>(fc_w, fc_b, (float*)d_out, n);
}